// round 5
// baseline (speedup 1.0000x reference)
#include <cuda_runtime.h>
#include <stdint.h>

#define N_MAX 50000
#define E_MAX 600000
#define SCAN_BLK 1024
#define NBLK_SCAN ((N_MAX + SCAN_BLK - 1) / SCAN_BLK)   // 49

// Scratch (device globals; no allocation allowed)
__device__ int   g_fmt;                 // 1 = int64 edge_index, 0 = int32
__device__ int   g_cnt[N_MAX];
__device__ int   g_off[N_MAX + 1];
__device__ int   g_pos[N_MAX];
__device__ int   g_bsum[NBLK_SCAN + 1];
__device__ float g_dinv[N_MAX];
__device__ int   g_csr[E_MAX];
__device__ float g_h[(size_t)N_MAX * 128];     // x @ W1
__device__ float g_agg[(size_t)N_MAX * 128];   // aggregated layer-1 (relu+bias fused)
__device__ float g_t[(size_t)N_MAX * 64];      // relu_h @ W2

// Packed f32x2 helpers (Blackwell sm_103a)
#define PACK_F32X2(out, lo, hi) \
    asm("mov.b64 %0, {%1, %2};" : "=l"(out) : "f"(lo), "f"(hi))
#define UNPACK_F32X2(lo, hi, in) \
    asm("mov.b64 {%0, %1}, %2;" : "=f"(lo), "=f"(hi) : "l"(in))
#define FMA_F32X2(d, a, b, c) \
    asm("fma.rn.f32x2 %0, %1, %2, %3;" : "=l"(d) : "l"(a), "l"(b), "l"(c))

// ---------------------------------------------------------------------------
// cnt zero + dtype detection (fused)
// ---------------------------------------------------------------------------
__global__ void k_init_detect(const int* __restrict__ raw, int E, int n) {
    int i = blockIdx.x * blockDim.x + threadIdx.x;
    if (i < n) g_cnt[i] = 0;
    if (blockIdx.x == 0) {
        __shared__ int any_hi;
        if (threadIdx.x == 0) any_hi = 0;
        __syncthreads();
        int samples = E < 4096 ? E : 4096;
        int local = 0;
        for (int j = threadIdx.x; j < samples; j += blockDim.x) {
            if (raw[2 * j + 1] != 0) local = 1;   // int64 high words are 0
        }
        if (local) any_hi = 1;
        __syncthreads();
        if (threadIdx.x == 0) g_fmt = (any_hi == 0) ? 1 : 0;
    }
}

// ---------------------------------------------------------------------------
// CSR build (convert-from-raw fused into count and fill)
// ---------------------------------------------------------------------------
__global__ void k_count_f(const int* __restrict__ raw, int E, int n) {
    int e = blockIdx.x * blockDim.x + threadIdx.x;
    if (e >= E) return;
    int d = g_fmt ? raw[2 * (E + e)] : raw[E + e];
    d = min(max(d, 0), n - 1);
    atomicAdd(&g_cnt[d], 1);
}

__global__ void __launch_bounds__(SCAN_BLK) k_scan_block(int n) {
    __shared__ int sh[SCAN_BLK];
    int t = threadIdx.x;
    int i = blockIdx.x * SCAN_BLK + t;
    int v = (i < n) ? g_cnt[i] : 0;
    sh[t] = v;
    __syncthreads();
#pragma unroll
    for (int d = 1; d < SCAN_BLK; d <<= 1) {
        int x = (t >= d) ? sh[t - d] : 0;
        __syncthreads();
        sh[t] += x;
        __syncthreads();
    }
    if (i < n) g_off[i] = sh[t] - v;
    if (t == SCAN_BLK - 1) g_bsum[blockIdx.x] = sh[t];
}

__global__ void k_scan_top() {
    if (threadIdx.x == 0) {
        int acc = 0;
        for (int b = 0; b < NBLK_SCAN; b++) {
            int v = g_bsum[b];
            g_bsum[b] = acc;
            acc += v;
        }
    }
}

__global__ void k_scan_add(int n, int E) {
    int i = blockIdx.x * blockDim.x + threadIdx.x;
    if (i < n) {
        int o = g_off[i] + g_bsum[i / SCAN_BLK];
        g_off[i] = o;
        g_pos[i] = o;
        g_dinv[i] = rsqrtf((float)g_cnt[i] + 1.0f);  // +1 self loop
    }
    if (i == 0) g_off[n] = E;
}

__global__ void k_fill_f(const int* __restrict__ raw, int E, int n) {
    int e = blockIdx.x * blockDim.x + threadIdx.x;
    if (e >= E) return;
    int fmt = g_fmt;
    int s = fmt ? raw[2 * e] : raw[e];
    int d = fmt ? raw[2 * (E + e)] : raw[E + e];
    s = min(max(s, 0), n - 1);
    d = min(max(d, 0), n - 1);
    int p = atomicAdd(&g_pos[d], 1);
    g_csr[p] = s;
}

// ---------------------------------------------------------------------------
// Packed-f32x2 register-tiled GEMM: H[n, OUTC] = X[n,128] @ W[128, OUTC].
// Block: 128 rows x OUTC cols, 256 threads.
// Micro-tile per thread: 8 rows x (OUTC/16) cols, accumulated as row-pairs
// in f32x2 (low word = even row, high word = odd row).
// ---------------------------------------------------------------------------
template <int OUTC>
__global__ void __launch_bounds__(256) k_gemm_f2(const float* __restrict__ X,
                                                 const float* __restrict__ W,
                                                 float* __restrict__ H, int n) {
    constexpr int TC = OUTC / 16;        // cols per thread (8 or 4)
    __shared__ float Xs[16][128];        // k-major
    __shared__ float Ws[16][OUTC];
    const int row0 = blockIdx.x * 128;
    const int tid  = threadIdx.x;
    const int tx   = tid & 15;           // col group
    const int ty   = tid >> 4;           // row group (8 rows)

    unsigned long long a2[4][TC];
#pragma unroll
    for (int rp = 0; rp < 4; rp++)
#pragma unroll
        for (int c = 0; c < TC; c++) a2[rp][c] = 0ull;

    for (int k0 = 0; k0 < 128; k0 += 16) {
        // X tile: 128 rows x 16 k, transposed into k-major (512 float4 loads)
#pragma unroll
        for (int f = tid; f < 512; f += 256) {
            int r  = f >> 2;
            int kq = f & 3;
            int gr = min(row0 + r, n - 1);
            float4 v = *(const float4*)&X[(size_t)gr * 128 + k0 + kq * 4];
            Xs[kq * 4 + 0][r] = v.x;
            Xs[kq * 4 + 1][r] = v.y;
            Xs[kq * 4 + 2][r] = v.z;
            Xs[kq * 4 + 3][r] = v.w;
        }
        // W tile: 16 k x OUTC cols
#pragma unroll
        for (int f = tid; f < 4 * OUTC; f += 256) {
            int kk = f / (OUTC / 4);
            int cq = f % (OUTC / 4);
            *(float4*)&Ws[kk][cq * 4] =
                *(const float4*)&W[(size_t)(k0 + kk) * OUTC + cq * 4];
        }
        __syncthreads();

#pragma unroll
        for (int k = 0; k < 16; k++) {
            // 8 rows = 4 row-pairs, read directly as packed u64
            ulonglong2 xa = *(ulonglong2*)&Xs[k][ty * 8];
            ulonglong2 xb = *(ulonglong2*)&Xs[k][ty * 8 + 4];
            unsigned long long xp[4] = {xa.x, xa.y, xb.x, xb.y};
            // TC cols, duplicated into both f32x2 lanes
            unsigned long long wd[TC];
#pragma unroll
            for (int c = 0; c < TC; c += 4) {
                float4 wv = *(float4*)&Ws[k][tx * TC + c];
                PACK_F32X2(wd[c + 0], wv.x, wv.x);
                PACK_F32X2(wd[c + 1], wv.y, wv.y);
                PACK_F32X2(wd[c + 2], wv.z, wv.z);
                PACK_F32X2(wd[c + 3], wv.w, wv.w);
            }
#pragma unroll
            for (int rp = 0; rp < 4; rp++)
#pragma unroll
                for (int c = 0; c < TC; c++)
                    FMA_F32X2(a2[rp][c], xp[rp], wd[c], a2[rp][c]);
        }
        __syncthreads();
    }

    // epilogue: unpack row-pairs and store
#pragma unroll
    for (int rp = 0; rp < 4; rp++) {
        float lo[TC], hi[TC];
#pragma unroll
        for (int c = 0; c < TC; c++) UNPACK_F32X2(lo[c], hi[c], a2[rp][c]);
        int re = row0 + ty * 8 + rp * 2;
        if (re < n) {
#pragma unroll
            for (int c = 0; c < TC; c += 4)
                *(float4*)&H[(size_t)re * OUTC + tx * TC + c] =
                    make_float4(lo[c], lo[c + 1], lo[c + 2], lo[c + 3]);
        }
        if (re + 1 < n) {
#pragma unroll
            for (int c = 0; c < TC; c += 4)
                *(float4*)&H[(size_t)(re + 1) * OUTC + tx * TC + c] =
                    make_float4(hi[c], hi[c + 1], hi[c + 2], hi[c + 3]);
        }
    }
}

// ---------------------------------------------------------------------------
// Aggregation: one warp per dst node, CSR gather, no atomics, 2-way unroll.
// Fuses self-loop, bias, (relu), store.
// ---------------------------------------------------------------------------
template <int CH, bool RELU>
__global__ void __launch_bounds__(256) k_agg(const float* __restrict__ H,
                                             float* __restrict__ OUT,
                                             const float* __restrict__ bias,
                                             int n) {
    int node = blockIdx.x * 8 + (threadIdx.x >> 5);
    int lane = threadIdx.x & 31;
    if (node >= n) return;

    float di = g_dinv[node];
    int beg = g_off[node];
    int end = g_off[node + 1];

    if (CH == 128) {
        float4 acc = ((const float4*)(H + (size_t)node * 128))[lane];  // self loop
        float ns = di * di;
        acc.x *= ns; acc.y *= ns; acc.z *= ns; acc.w *= ns;
        int j = beg;
        for (; j + 1 < end; j += 2) {
            int s0 = g_csr[j], s1 = g_csr[j + 1];
            float n0 = g_dinv[s0] * di, n1 = g_dinv[s1] * di;
            float4 v0 = ((const float4*)(H + (size_t)s0 * 128))[lane];
            float4 v1 = ((const float4*)(H + (size_t)s1 * 128))[lane];
            acc.x += v0.x * n0 + v1.x * n1;
            acc.y += v0.y * n0 + v1.y * n1;
            acc.z += v0.z * n0 + v1.z * n1;
            acc.w += v0.w * n0 + v1.w * n1;
        }
        if (j < end) {
            int s = g_csr[j];
            float nm = g_dinv[s] * di;
            float4 v = ((const float4*)(H + (size_t)s * 128))[lane];
            acc.x += v.x * nm; acc.y += v.y * nm;
            acc.z += v.z * nm; acc.w += v.w * nm;
        }
        int c = lane * 4;
        acc.x += __ldg(&bias[c]);     acc.y += __ldg(&bias[c + 1]);
        acc.z += __ldg(&bias[c + 2]); acc.w += __ldg(&bias[c + 3]);
        if (RELU) {
            acc.x = fmaxf(acc.x, 0.f); acc.y = fmaxf(acc.y, 0.f);
            acc.z = fmaxf(acc.z, 0.f); acc.w = fmaxf(acc.w, 0.f);
        }
        ((float4*)(OUT + (size_t)node * 128))[lane] = acc;
    } else {
        float2 acc = ((const float2*)(H + (size_t)node * 64))[lane];
        float ns = di * di;
        acc.x *= ns; acc.y *= ns;
        int j = beg;
        for (; j + 1 < end; j += 2) {
            int s0 = g_csr[j], s1 = g_csr[j + 1];
            float n0 = g_dinv[s0] * di, n1 = g_dinv[s1] * di;
            float2 v0 = ((const float2*)(H + (size_t)s0 * 64))[lane];
            float2 v1 = ((const float2*)(H + (size_t)s1 * 64))[lane];
            acc.x += v0.x * n0 + v1.x * n1;
            acc.y += v0.y * n0 + v1.y * n1;
        }
        if (j < end) {
            int s = g_csr[j];
            float nm = g_dinv[s] * di;
            float2 v = ((const float2*)(H + (size_t)s * 64))[lane];
            acc.x += v.x * nm; acc.y += v.y * nm;
        }
        int c = lane * 2;
        acc.x += __ldg(&bias[c]); acc.y += __ldg(&bias[c + 1]);
        if (RELU) { acc.x = fmaxf(acc.x, 0.f); acc.y = fmaxf(acc.y, 0.f); }
        ((float2*)(OUT + (size_t)node * 64))[lane] = acc;
    }
}

// ---------------------------------------------------------------------------
extern "C" void kernel_launch(void* const* d_in, const int* in_sizes, int n_in,
                              void* d_out, int out_size) {
    const float* x   = (const float*)d_in[0];
    const int*   ei  = (const int*)d_in[1];   // int32 OR int64 (auto-detected)
    const float* W1  = (const float*)d_in[2];
    const float* b1  = (const float*)d_in[3];
    const float* W2  = (const float*)d_in[4];
    const float* b2  = (const float*)d_in[5];
    float*       out = (float*)d_out;

    const int n = in_sizes[0] / 128;
    const int E = in_sizes[1] / 2;

    float* d_h;   cudaGetSymbolAddress((void**)&d_h,   g_h);
    float* d_agg; cudaGetSymbolAddress((void**)&d_agg, g_agg);
    float* d_t;   cudaGetSymbolAddress((void**)&d_t,   g_t);

    const int T = 256;

    // 0) zero counters + detect edge dtype (fused)
    k_init_detect<<<(n + T - 1) / T, T>>>(ei, E, n);

    // 1) CSR build + dinv
    k_count_f<<<(E + T - 1) / T, T>>>(ei, E, n);
    k_scan_block<<<NBLK_SCAN, SCAN_BLK>>>(n);
    k_scan_top<<<1, 32>>>();
    k_scan_add<<<(n + T - 1) / T, T>>>(n, E);
    k_fill_f<<<(E + T - 1) / T, T>>>(ei, E, n);

    // 2) layer 1: h = x @ W1 (f32x2 packed GEMM)
    k_gemm_f2<128><<<(n + 127) / 128, 256>>>(x, W1, d_h, n);

    // 3) aggregate layer 1 (fused self-loop + bias + relu)
    k_agg<128, true><<<(n + 7) / 8, 256>>>(d_h, d_agg, b1, n);

    // 4) layer 2: t = relu_h @ W2
    k_gemm_f2<64><<<(n + 127) / 128, 256>>>(d_agg, W2, d_t, n);

    // 5) aggregate layer 2 directly into d_out (fused bias)
    k_agg<64, false><<<(n + 7) / 8, 256>>>(d_t, out, b2, n);
}

// round 6
// speedup vs baseline: 1.1574x; 1.1574x over previous
#include <cuda_runtime.h>
#include <stdint.h>

#define N_MAX 50000
#define E_MAX 600000
#define SCAN_BLK 1024
#define NBLK_SCAN ((N_MAX + SCAN_BLK - 1) / SCAN_BLK)   // 49

// Scratch (device globals; no allocation allowed)
__device__ int   g_fmt;                 // 1 = int64 edge_index, 0 = int32
__device__ int   g_cnt[N_MAX];
__device__ int   g_off[N_MAX + 1];
__device__ int   g_pos[N_MAX];
__device__ int   g_bsum[NBLK_SCAN + 1];
__device__ float g_dinv[N_MAX];
__device__ int   g_csr[E_MAX];
__device__ float g_h[(size_t)N_MAX * 128];     // x @ W1
__device__ float g_agg[(size_t)N_MAX * 128];   // aggregated layer-1 (relu+bias fused)
__device__ float g_t[(size_t)N_MAX * 64];      // relu_h @ W2

// ---------------------------------------------------------------------------
// cnt zero + dtype detection (fused)
// ---------------------------------------------------------------------------
__global__ void k_init_detect(const int* __restrict__ raw, int E, int n) {
    int i = blockIdx.x * blockDim.x + threadIdx.x;
    if (i < n) g_cnt[i] = 0;
    if (blockIdx.x == 0) {
        __shared__ int any_hi;
        if (threadIdx.x == 0) any_hi = 0;
        __syncthreads();
        int samples = E < 4096 ? E : 4096;
        int local = 0;
        for (int j = threadIdx.x; j < samples; j += blockDim.x) {
            if (raw[2 * j + 1] != 0) local = 1;   // int64 high words are 0
        }
        if (local) any_hi = 1;
        __syncthreads();
        if (threadIdx.x == 0) g_fmt = (any_hi == 0) ? 1 : 0;
    }
}

// ---------------------------------------------------------------------------
// CSR build (convert-from-raw fused into count and fill)
// ---------------------------------------------------------------------------
__global__ void k_count_f(const int* __restrict__ raw, int E, int n) {
    int e = blockIdx.x * blockDim.x + threadIdx.x;
    if (e >= E) return;
    int d = g_fmt ? raw[2 * (E + e)] : raw[E + e];
    d = min(max(d, 0), n - 1);
    atomicAdd(&g_cnt[d], 1);
}

__global__ void __launch_bounds__(SCAN_BLK) k_scan_block(int n) {
    __shared__ int sh[SCAN_BLK];
    int t = threadIdx.x;
    int i = blockIdx.x * SCAN_BLK + t;
    int v = (i < n) ? g_cnt[i] : 0;
    sh[t] = v;
    __syncthreads();
#pragma unroll
    for (int d = 1; d < SCAN_BLK; d <<= 1) {
        int x = (t >= d) ? sh[t - d] : 0;
        __syncthreads();
        sh[t] += x;
        __syncthreads();
    }
    if (i < n) g_off[i] = sh[t] - v;
    if (t == SCAN_BLK - 1) g_bsum[blockIdx.x] = sh[t];
}

// parallel scan of the 49 block sums (one block of 64 threads)
__global__ void k_scan_top() {
    __shared__ int sh[64];
    int t = threadIdx.x;
    int v = (t < NBLK_SCAN) ? g_bsum[t] : 0;
    sh[t] = v;
    __syncthreads();
#pragma unroll
    for (int d = 1; d < 64; d <<= 1) {
        int x = (t >= d) ? sh[t - d] : 0;
        __syncthreads();
        sh[t] += x;
        __syncthreads();
    }
    if (t < NBLK_SCAN) g_bsum[t] = sh[t] - v;   // exclusive
}

__global__ void k_scan_add(int n, int E) {
    int i = blockIdx.x * blockDim.x + threadIdx.x;
    if (i < n) {
        int o = g_off[i] + g_bsum[i / SCAN_BLK];
        g_off[i] = o;
        g_pos[i] = o;
        g_dinv[i] = rsqrtf((float)g_cnt[i] + 1.0f);  // +1 self loop
    }
    if (i == 0) g_off[n] = E;
}

__global__ void k_fill_f(const int* __restrict__ raw, int E, int n) {
    int e = blockIdx.x * blockDim.x + threadIdx.x;
    if (e >= E) return;
    int fmt = g_fmt;
    int s = fmt ? raw[2 * e] : raw[e];
    int d = fmt ? raw[2 * (E + e)] : raw[E + e];
    s = min(max(s, 0), n - 1);
    d = min(max(d, 0), n - 1);
    int p = atomicAdd(&g_pos[d], 1);
    g_csr[p] = s;
}

// ---------------------------------------------------------------------------
// Register-tiled GEMM: H[n, OUTC] = X[n,128] @ W[128, OUTC].
// Block: 128 rows x 64 cols, 256 threads, 8x4 micro-tile per thread. (R4 proven)
// ---------------------------------------------------------------------------
template <int OUTC>
__global__ void __launch_bounds__(256) k_gemm_rt(const float* __restrict__ X,
                                                 const float* __restrict__ W,
                                                 float* __restrict__ H, int n) {
    __shared__ float Xs[16][128];   // k-major
    __shared__ float Ws[16][64];
    const int co   = blockIdx.y * 64;
    const int row0 = blockIdx.x * 128;
    const int tid  = threadIdx.x;
    const int tx   = tid & 15;      // col group: 4 cols
    const int ty   = tid >> 4;      // row group: 8 rows

    float acc[8][4];
#pragma unroll
    for (int i = 0; i < 8; i++)
#pragma unroll
        for (int j = 0; j < 4; j++) acc[i][j] = 0.f;

    for (int k0 = 0; k0 < 128; k0 += 16) {
#pragma unroll
        for (int f = tid; f < 512; f += 256) {
            int r  = f >> 2;
            int kq = f & 3;
            int gr = min(row0 + r, n - 1);
            float4 v = *(const float4*)&X[(size_t)gr * 128 + k0 + kq * 4];
            Xs[kq * 4 + 0][r] = v.x;
            Xs[kq * 4 + 1][r] = v.y;
            Xs[kq * 4 + 2][r] = v.z;
            Xs[kq * 4 + 3][r] = v.w;
        }
        {
            int kk = tid >> 4;
            int cq = tid & 15;
            *(float4*)&Ws[kk][cq * 4] =
                *(const float4*)&W[(size_t)(k0 + kk) * OUTC + co + cq * 4];
        }
        __syncthreads();

#pragma unroll
        for (int k = 0; k < 16; k++) {
            float xr[8];
            *(float4*)&xr[0] = *(float4*)&Xs[k][ty * 8];
            *(float4*)&xr[4] = *(float4*)&Xs[k][ty * 8 + 4];
            float4 wv = *(float4*)&Ws[k][tx * 4];
#pragma unroll
            for (int i = 0; i < 8; i++) {
                acc[i][0] += xr[i] * wv.x;
                acc[i][1] += xr[i] * wv.y;
                acc[i][2] += xr[i] * wv.z;
                acc[i][3] += xr[i] * wv.w;
            }
        }
        __syncthreads();
    }

#pragma unroll
    for (int i = 0; i < 8; i++) {
        int gr = row0 + ty * 8 + i;
        if (gr < n)
            *(float4*)&H[(size_t)gr * OUTC + co + tx * 4] = *(float4*)&acc[i][0];
    }
}

// ---------------------------------------------------------------------------
// Aggregation: one warp per dst node, CSR gather, no atomics, 2-way unroll.
// ---------------------------------------------------------------------------
template <int CH, bool RELU>
__global__ void __launch_bounds__(256) k_agg(const float* __restrict__ H,
                                             float* __restrict__ OUT,
                                             const float* __restrict__ bias,
                                             int n) {
    int node = blockIdx.x * 8 + (threadIdx.x >> 5);
    int lane = threadIdx.x & 31;
    if (node >= n) return;

    float di = g_dinv[node];
    int beg = g_off[node];
    int end = g_off[node + 1];

    if (CH == 128) {
        float4 acc = ((const float4*)(H + (size_t)node * 128))[lane];  // self loop
        float ns = di * di;
        acc.x *= ns; acc.y *= ns; acc.z *= ns; acc.w *= ns;
        int j = beg;
        for (; j + 1 < end; j += 2) {
            int s0 = g_csr[j], s1 = g_csr[j + 1];
            float n0 = g_dinv[s0] * di, n1 = g_dinv[s1] * di;
            float4 v0 = ((const float4*)(H + (size_t)s0 * 128))[lane];
            float4 v1 = ((const float4*)(H + (size_t)s1 * 128))[lane];
            acc.x += v0.x * n0 + v1.x * n1;
            acc.y += v0.y * n0 + v1.y * n1;
            acc.z += v0.z * n0 + v1.z * n1;
            acc.w += v0.w * n0 + v1.w * n1;
        }
        if (j < end) {
            int s = g_csr[j];
            float nm = g_dinv[s] * di;
            float4 v = ((const float4*)(H + (size_t)s * 128))[lane];
            acc.x += v.x * nm; acc.y += v.y * nm;
            acc.z += v.z * nm; acc.w += v.w * nm;
        }
        int c = lane * 4;
        acc.x += __ldg(&bias[c]);     acc.y += __ldg(&bias[c + 1]);
        acc.z += __ldg(&bias[c + 2]); acc.w += __ldg(&bias[c + 3]);
        if (RELU) {
            acc.x = fmaxf(acc.x, 0.f); acc.y = fmaxf(acc.y, 0.f);
            acc.z = fmaxf(acc.z, 0.f); acc.w = fmaxf(acc.w, 0.f);
        }
        ((float4*)(OUT + (size_t)node * 128))[lane] = acc;
    } else {
        float2 acc = ((const float2*)(H + (size_t)node * 64))[lane];
        float ns = di * di;
        acc.x *= ns; acc.y *= ns;
        int j = beg;
        for (; j + 1 < end; j += 2) {
            int s0 = g_csr[j], s1 = g_csr[j + 1];
            float n0 = g_dinv[s0] * di, n1 = g_dinv[s1] * di;
            float2 v0 = ((const float2*)(H + (size_t)s0 * 64))[lane];
            float2 v1 = ((const float2*)(H + (size_t)s1 * 64))[lane];
            acc.x += v0.x * n0 + v1.x * n1;
            acc.y += v0.y * n0 + v1.y * n1;
        }
        if (j < end) {
            int s = g_csr[j];
            float nm = g_dinv[s] * di;
            float2 v = ((const float2*)(H + (size_t)s * 64))[lane];
            acc.x += v.x * nm; acc.y += v.y * nm;
        }
        int c = lane * 2;
        acc.x += __ldg(&bias[c]); acc.y += __ldg(&bias[c + 1]);
        if (RELU) { acc.x = fmaxf(acc.x, 0.f); acc.y = fmaxf(acc.y, 0.f); }
        ((float2*)(OUT + (size_t)node * 64))[lane] = acc;
    }
}

// ---------------------------------------------------------------------------
extern "C" void kernel_launch(void* const* d_in, const int* in_sizes, int n_in,
                              void* d_out, int out_size) {
    const float* x   = (const float*)d_in[0];
    const int*   ei  = (const int*)d_in[1];   // int32 OR int64 (auto-detected)
    const float* W1  = (const float*)d_in[2];
    const float* b1  = (const float*)d_in[3];
    const float* W2  = (const float*)d_in[4];
    const float* b2  = (const float*)d_in[5];
    float*       out = (float*)d_out;

    const int n = in_sizes[0] / 128;
    const int E = in_sizes[1] / 2;

    float* d_h;   cudaGetSymbolAddress((void**)&d_h,   g_h);
    float* d_agg; cudaGetSymbolAddress((void**)&d_agg, g_agg);
    float* d_t;   cudaGetSymbolAddress((void**)&d_t,   g_t);

    const int T = 256;

    // Side stream for GEMM1 (independent of CSR build) — fork/join via events
    // so the dependency structure is captured into the graph.
    cudaStream_t s1;
    cudaStreamCreateWithFlags(&s1, cudaStreamNonBlocking);
    cudaEvent_t e_fork, e_join;
    cudaEventCreateWithFlags(&e_fork, cudaEventDisableTiming);
    cudaEventCreateWithFlags(&e_join, cudaEventDisableTiming);

    // fork: GEMM1 on s1
    cudaEventRecord(e_fork, 0);
    cudaStreamWaitEvent(s1, e_fork, 0);
    {
        dim3 grid((n + 127) / 128, 2);
        k_gemm_rt<128><<<grid, 256, 0, s1>>>(x, W1, d_h, n);
    }
    cudaEventRecord(e_join, s1);

    // CSR build + dinv on the main (capturing) stream, concurrent with GEMM1
    k_init_detect<<<(n + T - 1) / T, T>>>(ei, E, n);
    k_count_f<<<(E + T - 1) / T, T>>>(ei, E, n);
    k_scan_block<<<NBLK_SCAN, SCAN_BLK>>>(n);
    k_scan_top<<<1, 64>>>();
    k_scan_add<<<(n + T - 1) / T, T>>>(n, E);
    k_fill_f<<<(E + T - 1) / T, T>>>(ei, E, n);

    // join: aggregation needs both CSR and g_h
    cudaStreamWaitEvent(0, e_join, 0);

    // aggregate layer 1 (fused self-loop + bias + relu)
    k_agg<128, true><<<(n + 7) / 8, 256>>>(d_h, d_agg, b1, n);

    // layer 2: t = relu_h @ W2
    {
        dim3 grid((n + 127) / 128, 1);
        k_gemm_rt<64><<<grid, 256>>>(d_agg, W2, d_t, n);
    }

    // aggregate layer 2 directly into d_out (fused bias)
    k_agg<64, false><<<(n + 7) / 8, 256>>>(d_t, out, b2, n);

    cudaEventDestroy(e_fork);
    cudaEventDestroy(e_join);
    cudaStreamDestroy(s1);
}

// round 7
// speedup vs baseline: 1.3783x; 1.1909x over previous
#include <cuda_runtime.h>
#include <stdint.h>

#define N_MAX 50000
#define E_MAX 600000
#define SCAN_BLK 1024
#define NBLK_SCAN ((N_MAX + SCAN_BLK - 1) / SCAN_BLK)   // 49

// Scratch (device globals; no allocation allowed)
__device__ int   g_fmt;                 // 1 = int64 edge_index, 0 = int32
__device__ int   g_cnt[N_MAX];
__device__ int   g_off[N_MAX + 1];
__device__ int   g_pos[N_MAX];
__device__ int   g_bsum[NBLK_SCAN + 1];
__device__ float g_dinv[N_MAX];
__device__ int   g_csr[E_MAX];
__device__ float g_h[(size_t)N_MAX * 128];     // x @ W1
__device__ float g_agg[(size_t)N_MAX * 128];   // aggregated layer-1 (relu+bias fused)
__device__ float g_t[(size_t)N_MAX * 64];      // relu_h @ W2

__device__ __forceinline__ float tf32r(float x) {
    uint32_t u;
    asm("cvt.rna.tf32.f32 %0, %1;" : "=r"(u) : "f"(x));
    return __uint_as_float(u);
}

__device__ __forceinline__ void mma_tf32(float* c, const uint32_t* a, const uint32_t* b) {
    asm volatile(
        "mma.sync.aligned.m16n8k8.row.col.f32.tf32.tf32.f32 "
        "{%0,%1,%2,%3}, {%4,%5,%6,%7}, {%8,%9}, {%0,%1,%2,%3};"
        : "+f"(c[0]), "+f"(c[1]), "+f"(c[2]), "+f"(c[3])
        : "r"(a[0]), "r"(a[1]), "r"(a[2]), "r"(a[3]), "r"(b[0]), "r"(b[1]));
}

// ---------------------------------------------------------------------------
// cnt zero + dtype detection (fused)
// ---------------------------------------------------------------------------
__global__ void k_init_detect(const int* __restrict__ raw, int E, int n) {
    int i = blockIdx.x * blockDim.x + threadIdx.x;
    if (i < n) g_cnt[i] = 0;
    if (blockIdx.x == 0) {
        __shared__ int any_hi;
        if (threadIdx.x == 0) any_hi = 0;
        __syncthreads();
        int samples = E < 4096 ? E : 4096;
        int local = 0;
        for (int j = threadIdx.x; j < samples; j += blockDim.x) {
            if (raw[2 * j + 1] != 0) local = 1;   // int64 high words are 0
        }
        if (local) any_hi = 1;
        __syncthreads();
        if (threadIdx.x == 0) g_fmt = (any_hi == 0) ? 1 : 0;
    }
}

// ---------------------------------------------------------------------------
// CSR build: 2 edges per thread, convert-from-raw fused
// ---------------------------------------------------------------------------
__global__ void k_count_f(const int* __restrict__ raw, int E, int n) {
    int e = 2 * (blockIdx.x * blockDim.x + threadIdx.x);
    if (e >= E) return;
    int fmt = g_fmt;
    bool two = (e + 1 < E);
    bool vec = two && ((E & 1) == 0);
    int d0, d1 = 0;
    if (fmt) {
        if (vec) { int4 v = *(const int4*)&raw[2 * (E + e)]; d0 = v.x; d1 = v.z; }
        else { d0 = raw[2 * (E + e)]; if (two) d1 = raw[2 * (E + e + 1)]; }
    } else {
        if (vec) { int2 v = *(const int2*)&raw[E + e]; d0 = v.x; d1 = v.y; }
        else { d0 = raw[E + e]; if (two) d1 = raw[E + e + 1]; }
    }
    d0 = min(max(d0, 0), n - 1);
    atomicAdd(&g_cnt[d0], 1);
    if (two) {
        d1 = min(max(d1, 0), n - 1);
        atomicAdd(&g_cnt[d1], 1);
    }
}

__global__ void __launch_bounds__(SCAN_BLK) k_scan_block(int n) {
    __shared__ int sh[SCAN_BLK];
    int t = threadIdx.x;
    int i = blockIdx.x * SCAN_BLK + t;
    int v = (i < n) ? g_cnt[i] : 0;
    sh[t] = v;
    __syncthreads();
#pragma unroll
    for (int d = 1; d < SCAN_BLK; d <<= 1) {
        int x = (t >= d) ? sh[t - d] : 0;
        __syncthreads();
        sh[t] += x;
        __syncthreads();
    }
    if (i < n) g_off[i] = sh[t] - v;
    if (t == SCAN_BLK - 1) g_bsum[blockIdx.x] = sh[t];
}

__global__ void k_scan_top() {
    __shared__ int sh[64];
    int t = threadIdx.x;
    int v = (t < NBLK_SCAN) ? g_bsum[t] : 0;
    sh[t] = v;
    __syncthreads();
#pragma unroll
    for (int d = 1; d < 64; d <<= 1) {
        int x = (t >= d) ? sh[t - d] : 0;
        __syncthreads();
        sh[t] += x;
        __syncthreads();
    }
    if (t < NBLK_SCAN) g_bsum[t] = sh[t] - v;   // exclusive
}

__global__ void k_scan_add(int n, int E) {
    int i = blockIdx.x * blockDim.x + threadIdx.x;
    if (i < n) {
        int o = g_off[i] + g_bsum[i / SCAN_BLK];
        g_off[i] = o;
        g_pos[i] = o;
        g_dinv[i] = rsqrtf((float)g_cnt[i] + 1.0f);  // +1 self loop
    }
    if (i == 0) g_off[n] = E;
}

__global__ void k_fill_f(const int* __restrict__ raw, int E, int n) {
    int e = 2 * (blockIdx.x * blockDim.x + threadIdx.x);
    if (e >= E) return;
    int fmt = g_fmt;
    bool two = (e + 1 < E);
    bool vec = two && ((E & 1) == 0);
    int s0, d0, s1 = 0, d1 = 0;
    if (fmt) {
        if (vec) {
            int4 sv = *(const int4*)&raw[2 * e];       s0 = sv.x; s1 = sv.z;
            int4 dv = *(const int4*)&raw[2 * (E + e)]; d0 = dv.x; d1 = dv.z;
        } else {
            s0 = raw[2 * e]; d0 = raw[2 * (E + e)];
            if (two) { s1 = raw[2 * (e + 1)]; d1 = raw[2 * (E + e + 1)]; }
        }
    } else {
        if (vec) {
            int2 sv = *(const int2*)&raw[e];     s0 = sv.x; s1 = sv.y;
            int2 dv = *(const int2*)&raw[E + e]; d0 = dv.x; d1 = dv.y;
        } else {
            s0 = raw[e]; d0 = raw[E + e];
            if (two) { s1 = raw[e + 1]; d1 = raw[E + e + 1]; }
        }
    }
    s0 = min(max(s0, 0), n - 1); d0 = min(max(d0, 0), n - 1);
    int p = atomicAdd(&g_pos[d0], 1);
    g_csr[p] = s0;
    if (two) {
        s1 = min(max(s1, 0), n - 1); d1 = min(max(d1, 0), n - 1);
        p = atomicAdd(&g_pos[d1], 1);
        g_csr[p] = s1;
    }
}

// ---------------------------------------------------------------------------
// tf32 tensor-core GEMM: H[n, OUTC] = X[n,128] @ W[128, OUTC]  (X stride 128)
// CTA tile 256x64, 8 warps (4M x 2N), warp tile 64x32, K sliced by 16.
// A/B staged in SMEM in exact m16n8k8 fragment order (padded groups).
// ---------------------------------------------------------------------------
template <int OUTC>
__global__ void __launch_bounds__(256) k_gemm_mma(const float* __restrict__ X,
                                                  const float* __restrict__ W,
                                                  float* __restrict__ H, int n) {
    __shared__ float As[32 * 33 * 4];   // 32 groups (block16 x kstep) of 32(+1 pad) float4
    __shared__ float Bs[16 * 33 * 2];   // 16 groups (nsub x kstep) of 32(+1 pad) float2
    const int tid   = threadIdx.x;
    const int lane  = tid & 31;
    const int warp  = tid >> 5;
    const int warpM = warp & 3;     // 0..3 -> 64-row slice
    const int warpN = warp >> 2;    // 0..1 -> 32-col slice
    const int row0  = blockIdx.x * 256;
    const int co    = blockIdx.y * 64;

    float c[4][4][4];
#pragma unroll
    for (int i = 0; i < 4; i++)
#pragma unroll
        for (int j = 0; j < 4; j++)
#pragma unroll
            for (int r = 0; r < 4; r++) c[i][j][r] = 0.f;

    for (int k0 = 0; k0 < 128; k0 += 16) {
        // --- stage A: 256 rows x 16 k, scattered into fragment order ---
#pragma unroll
        for (int f = tid; f < 1024; f += 256) {
            int r  = f >> 2;
            int kq = f & 3;                    // k quad: k = kq*4 + j
            int gr = min(row0 + r, n - 1);
            float4 v = *(const float4*)&X[(size_t)gr * 128 + k0 + kq * 4];
            int grp  = (r >> 4) * 2 + (kq >> 1);           // block16*2 + kstep
            int lb   = (r & 7) * 4;                        // lane base
            int reg  = (kq & 1) * 2 + ((r >> 3) & 1);      // frag reg index
            int base = grp * 33 * 4;                       // float4-unit group, x4 floats
            As[(base + (lb + 0) * 4) + reg] = tf32r(v.x);
            As[(base + (lb + 1) * 4) + reg] = tf32r(v.y);
            As[(base + (lb + 2) * 4) + reg] = tf32r(v.z);
            As[(base + (lb + 3) * 4) + reg] = tf32r(v.w);
        }
        // --- stage B: 16 k x 64 n ---
        {
            int k  = tid >> 4;
            int nq = tid & 15;                 // n = nq*4 + j
            float4 v = *(const float4*)&W[(size_t)(k0 + k) * OUTC + co + nq * 4];
            int kstep = k >> 3, tg = k & 3, regb = (k >> 2) & 1;
            float vv[4] = {v.x, v.y, v.z, v.w};
#pragma unroll
            for (int j = 0; j < 4; j++) {
                int nn = nq * 4 + j;
                int grp = (nn >> 3) * 2 + kstep;
                Bs[(grp * 33 + (nn & 7) * 4 + tg) * 2 + regb] = tf32r(vv[j]);
            }
        }
        __syncthreads();

        // --- compute: 2 ksteps of 8 ---
#pragma unroll
        for (int ks = 0; ks < 2; ks++) {
            uint32_t a[4][4];
            uint32_t b[4][2];
#pragma unroll
            for (int m = 0; m < 4; m++) {
                float4 av = *(const float4*)&As[(((warpM * 4 + m) * 2 + ks) * 33 + lane) * 4];
                a[m][0] = __float_as_uint(av.x);
                a[m][1] = __float_as_uint(av.y);
                a[m][2] = __float_as_uint(av.z);
                a[m][3] = __float_as_uint(av.w);
            }
#pragma unroll
            for (int nb = 0; nb < 4; nb++) {
                float2 bv = *(const float2*)&Bs[(((warpN * 4 + nb) * 2 + ks) * 33 + lane) * 2];
                b[nb][0] = __float_as_uint(bv.x);
                b[nb][1] = __float_as_uint(bv.y);
            }
#pragma unroll
            for (int m = 0; m < 4; m++)
#pragma unroll
                for (int nb = 0; nb < 4; nb++)
                    mma_tf32(c[m][nb], a[m], b[nb]);
        }
        __syncthreads();
    }

    // --- epilogue ---
    const int g  = lane >> 2;
    const int tg = lane & 3;
#pragma unroll
    for (int m = 0; m < 4; m++) {
#pragma unroll
        for (int nb = 0; nb < 4; nb++) {
            int row = row0 + warpM * 64 + m * 16 + g;
            int col = co + warpN * 32 + nb * 8 + tg * 2;
            if (row < n)
                *(float2*)&H[(size_t)row * OUTC + col] = make_float2(c[m][nb][0], c[m][nb][1]);
            if (row + 8 < n)
                *(float2*)&H[(size_t)(row + 8) * OUTC + col] = make_float2(c[m][nb][2], c[m][nb][3]);
        }
    }
}

// ---------------------------------------------------------------------------
// Aggregation: one warp per dst node, CSR gather, no atomics, 2-way unroll.
// ---------------------------------------------------------------------------
template <int CH, bool RELU>
__global__ void __launch_bounds__(256) k_agg(const float* __restrict__ H,
                                             float* __restrict__ OUT,
                                             const float* __restrict__ bias,
                                             int n) {
    int node = blockIdx.x * 8 + (threadIdx.x >> 5);
    int lane = threadIdx.x & 31;
    if (node >= n) return;

    float di = g_dinv[node];
    int beg = g_off[node];
    int end = g_off[node + 1];

    if (CH == 128) {
        float4 acc = ((const float4*)(H + (size_t)node * 128))[lane];  // self loop
        float ns = di * di;
        acc.x *= ns; acc.y *= ns; acc.z *= ns; acc.w *= ns;
        int j = beg;
        for (; j + 1 < end; j += 2) {
            int s0 = g_csr[j], s1 = g_csr[j + 1];
            float n0 = g_dinv[s0] * di, n1 = g_dinv[s1] * di;
            float4 v0 = ((const float4*)(H + (size_t)s0 * 128))[lane];
            float4 v1 = ((const float4*)(H + (size_t)s1 * 128))[lane];
            acc.x += v0.x * n0 + v1.x * n1;
            acc.y += v0.y * n0 + v1.y * n1;
            acc.z += v0.z * n0 + v1.z * n1;
            acc.w += v0.w * n0 + v1.w * n1;
        }
        if (j < end) {
            int s = g_csr[j];
            float nm = g_dinv[s] * di;
            float4 v = ((const float4*)(H + (size_t)s * 128))[lane];
            acc.x += v.x * nm; acc.y += v.y * nm;
            acc.z += v.z * nm; acc.w += v.w * nm;
        }
        int cc = lane * 4;
        acc.x += __ldg(&bias[cc]);     acc.y += __ldg(&bias[cc + 1]);
        acc.z += __ldg(&bias[cc + 2]); acc.w += __ldg(&bias[cc + 3]);
        if (RELU) {
            acc.x = fmaxf(acc.x, 0.f); acc.y = fmaxf(acc.y, 0.f);
            acc.z = fmaxf(acc.z, 0.f); acc.w = fmaxf(acc.w, 0.f);
        }
        ((float4*)(OUT + (size_t)node * 128))[lane] = acc;
    } else {
        float2 acc = ((const float2*)(H + (size_t)node * 64))[lane];
        float ns = di * di;
        acc.x *= ns; acc.y *= ns;
        int j = beg;
        for (; j + 1 < end; j += 2) {
            int s0 = g_csr[j], s1 = g_csr[j + 1];
            float n0 = g_dinv[s0] * di, n1 = g_dinv[s1] * di;
            float2 v0 = ((const float2*)(H + (size_t)s0 * 64))[lane];
            float2 v1 = ((const float2*)(H + (size_t)s1 * 64))[lane];
            acc.x += v0.x * n0 + v1.x * n1;
            acc.y += v0.y * n0 + v1.y * n1;
        }
        if (j < end) {
            int s = g_csr[j];
            float nm = g_dinv[s] * di;
            float2 v = ((const float2*)(H + (size_t)s * 64))[lane];
            acc.x += v.x * nm; acc.y += v.y * nm;
        }
        int cc = lane * 2;
        acc.x += __ldg(&bias[cc]); acc.y += __ldg(&bias[cc + 1]);
        if (RELU) { acc.x = fmaxf(acc.x, 0.f); acc.y = fmaxf(acc.y, 0.f); }
        ((float2*)(OUT + (size_t)node * 64))[lane] = acc;
    }
}

// ---------------------------------------------------------------------------
extern "C" void kernel_launch(void* const* d_in, const int* in_sizes, int n_in,
                              void* d_out, int out_size) {
    const float* x   = (const float*)d_in[0];
    const int*   ei  = (const int*)d_in[1];   // int32 OR int64 (auto-detected)
    const float* W1  = (const float*)d_in[2];
    const float* b1  = (const float*)d_in[3];
    const float* W2  = (const float*)d_in[4];
    const float* b2  = (const float*)d_in[5];
    float*       out = (float*)d_out;

    const int n = in_sizes[0] / 128;
    const int E = in_sizes[1] / 2;

    float* d_h;   cudaGetSymbolAddress((void**)&d_h,   g_h);
    float* d_agg; cudaGetSymbolAddress((void**)&d_agg, g_agg);
    float* d_t;   cudaGetSymbolAddress((void**)&d_t,   g_t);

    const int T = 256;

    // Side stream for GEMM1 (independent of CSR build) — fork/join via events.
    cudaStream_t s1;
    cudaStreamCreateWithFlags(&s1, cudaStreamNonBlocking);
    cudaEvent_t e_fork, e_join;
    cudaEventCreateWithFlags(&e_fork, cudaEventDisableTiming);
    cudaEventCreateWithFlags(&e_join, cudaEventDisableTiming);

    cudaEventRecord(e_fork, 0);
    cudaStreamWaitEvent(s1, e_fork, 0);
    {
        dim3 grid((n + 255) / 256, 2);
        k_gemm_mma<128><<<grid, 256, 0, s1>>>(x, W1, d_h, n);
    }
    cudaEventRecord(e_join, s1);

    // CSR build + dinv on the main stream, concurrent with GEMM1
    k_init_detect<<<(n + T - 1) / T, T>>>(ei, E, n);
    {
        int halfE = (E + 1) / 2;
        k_count_f<<<(halfE + T - 1) / T, T>>>(ei, E, n);
    }
    k_scan_block<<<NBLK_SCAN, SCAN_BLK>>>(n);
    k_scan_top<<<1, 64>>>();
    k_scan_add<<<(n + T - 1) / T, T>>>(n, E);
    {
        int halfE = (E + 1) / 2;
        k_fill_f<<<(halfE + T - 1) / T, T>>>(ei, E, n);
    }

    cudaStreamWaitEvent(0, e_join, 0);

    // aggregate layer 1 (fused self-loop + bias + relu)
    k_agg<128, true><<<(n + 7) / 8, 256>>>(d_h, d_agg, b1, n);

    // layer 2: t = relu_h @ W2
    {
        dim3 grid((n + 255) / 256, 1);
        k_gemm_mma<64><<<grid, 256>>>(d_agg, W2, d_t, n);
    }

    // aggregate layer 2 directly into d_out (fused bias)
    k_agg<64, false><<<(n + 7) / 8, 256>>>(d_t, out, b2, n);

    cudaEventDestroy(e_fork);
    cudaEventDestroy(e_join);
    cudaStreamDestroy(s1);
}

// round 8
// speedup vs baseline: 1.4596x; 1.0590x over previous
#include <cuda_runtime.h>
#include <cuda_fp16.h>
#include <stdint.h>

#define N_MAX 50000
#define E_MAX 600000
#define SCAN_BLK 1024
#define NBLK_SCAN ((N_MAX + SCAN_BLK - 1) / SCAN_BLK)   // 49

// Scratch (device globals; no allocation allowed)
__device__ int    g_fmt;                 // 1 = int64 edge_index, 0 = int32
__device__ int    g_cnt[N_MAX];
__device__ int    g_off[N_MAX + 1];
__device__ int    g_pos[N_MAX];
__device__ int    g_bsum[NBLK_SCAN + 1];
__device__ float  g_dinv[N_MAX];
__device__ int    g_csr[E_MAX];
__device__ __half g_h[(size_t)N_MAX * 128];   // x @ W1 (fp16 for cheap gather)
__device__ float  g_agg[(size_t)N_MAX * 128]; // aggregated layer-1 (fp32, GEMM2 input)
__device__ __half g_t[(size_t)N_MAX * 64];    // relu_h @ W2 (fp16 for cheap gather)

__device__ __forceinline__ float tf32r(float x) {
    uint32_t u;
    asm("cvt.rna.tf32.f32 %0, %1;" : "=r"(u) : "f"(x));
    return __uint_as_float(u);
}

__device__ __forceinline__ void mma_tf32(float* c, const uint32_t* a, const uint32_t* b) {
    asm volatile(
        "mma.sync.aligned.m16n8k8.row.col.f32.tf32.tf32.f32 "
        "{%0,%1,%2,%3}, {%4,%5,%6,%7}, {%8,%9}, {%0,%1,%2,%3};"
        : "+f"(c[0]), "+f"(c[1]), "+f"(c[2]), "+f"(c[3])
        : "r"(a[0]), "r"(a[1]), "r"(a[2]), "r"(a[3]), "r"(b[0]), "r"(b[1]));
}

// ---------------------------------------------------------------------------
// cnt zero + dtype detection (fused)
// ---------------------------------------------------------------------------
__global__ void k_init_detect(const int* __restrict__ raw, int E, int n) {
    int i = blockIdx.x * blockDim.x + threadIdx.x;
    if (i < n) g_cnt[i] = 0;
    if (blockIdx.x == 0) {
        __shared__ int any_hi;
        if (threadIdx.x == 0) any_hi = 0;
        __syncthreads();
        int samples = E < 4096 ? E : 4096;
        int local = 0;
        for (int j = threadIdx.x; j < samples; j += blockDim.x) {
            if (raw[2 * j + 1] != 0) local = 1;   // int64 high words are 0
        }
        if (local) any_hi = 1;
        __syncthreads();
        if (threadIdx.x == 0) g_fmt = (any_hi == 0) ? 1 : 0;
    }
}

// ---------------------------------------------------------------------------
// CSR build: 2 edges per thread, convert-from-raw fused
// ---------------------------------------------------------------------------
__global__ void k_count_f(const int* __restrict__ raw, int E, int n) {
    int e = 2 * (blockIdx.x * blockDim.x + threadIdx.x);
    if (e >= E) return;
    int fmt = g_fmt;
    bool two = (e + 1 < E);
    bool vec = two && ((E & 1) == 0);
    int d0, d1 = 0;
    if (fmt) {
        if (vec) { int4 v = *(const int4*)&raw[2 * (E + e)]; d0 = v.x; d1 = v.z; }
        else { d0 = raw[2 * (E + e)]; if (two) d1 = raw[2 * (E + e + 1)]; }
    } else {
        if (vec) { int2 v = *(const int2*)&raw[E + e]; d0 = v.x; d1 = v.y; }
        else { d0 = raw[E + e]; if (two) d1 = raw[E + e + 1]; }
    }
    d0 = min(max(d0, 0), n - 1);
    atomicAdd(&g_cnt[d0], 1);
    if (two) {
        d1 = min(max(d1, 0), n - 1);
        atomicAdd(&g_cnt[d1], 1);
    }
}

// 2-level warp-shuffle scan (1024 threads = 32 warps)
__global__ void __launch_bounds__(SCAN_BLK) k_scan_block(int n) {
    __shared__ int warpsum[32];
    int t = threadIdx.x;
    int i = blockIdx.x * SCAN_BLK + t;
    int v = (i < n) ? g_cnt[i] : 0;
    int lane = t & 31, w = t >> 5;
    int x = v;
#pragma unroll
    for (int d = 1; d < 32; d <<= 1) {
        int y = __shfl_up_sync(0xFFFFFFFFu, x, d);
        if (lane >= d) x += y;
    }
    if (lane == 31) warpsum[w] = x;
    __syncthreads();
    if (w == 0) {
        int s = warpsum[lane];
#pragma unroll
        for (int d = 1; d < 32; d <<= 1) {
            int y = __shfl_up_sync(0xFFFFFFFFu, s, d);
            if (lane >= d) s += y;
        }
        warpsum[lane] = s;
    }
    __syncthreads();
    int base = (w > 0) ? warpsum[w - 1] : 0;
    if (i < n) g_off[i] = base + x - v;         // exclusive
    if (t == SCAN_BLK - 1) g_bsum[blockIdx.x] = base + x;
}

__global__ void k_scan_top() {
    __shared__ int sh[64];
    int t = threadIdx.x;
    int v = (t < NBLK_SCAN) ? g_bsum[t] : 0;
    sh[t] = v;
    __syncthreads();
#pragma unroll
    for (int d = 1; d < 64; d <<= 1) {
        int x = (t >= d) ? sh[t - d] : 0;
        __syncthreads();
        sh[t] += x;
        __syncthreads();
    }
    if (t < NBLK_SCAN) g_bsum[t] = sh[t] - v;   // exclusive
}

__global__ void k_scan_add(int n, int E) {
    int i = blockIdx.x * blockDim.x + threadIdx.x;
    if (i < n) {
        int o = g_off[i] + g_bsum[i / SCAN_BLK];
        g_off[i] = o;
        g_pos[i] = o;
        g_dinv[i] = rsqrtf((float)g_cnt[i] + 1.0f);  // +1 self loop
    }
    if (i == 0) g_off[n] = E;
}

__global__ void k_fill_f(const int* __restrict__ raw, int E, int n) {
    int e = 2 * (blockIdx.x * blockDim.x + threadIdx.x);
    if (e >= E) return;
    int fmt = g_fmt;
    bool two = (e + 1 < E);
    bool vec = two && ((E & 1) == 0);
    int s0, d0, s1 = 0, d1 = 0;
    if (fmt) {
        if (vec) {
            int4 sv = *(const int4*)&raw[2 * e];       s0 = sv.x; s1 = sv.z;
            int4 dv = *(const int4*)&raw[2 * (E + e)]; d0 = dv.x; d1 = dv.z;
        } else {
            s0 = raw[2 * e]; d0 = raw[2 * (E + e)];
            if (two) { s1 = raw[2 * (e + 1)]; d1 = raw[2 * (E + e + 1)]; }
        }
    } else {
        if (vec) {
            int2 sv = *(const int2*)&raw[e];     s0 = sv.x; s1 = sv.y;
            int2 dv = *(const int2*)&raw[E + e]; d0 = dv.x; d1 = dv.y;
        } else {
            s0 = raw[e]; d0 = raw[E + e];
            if (two) { s1 = raw[e + 1]; d1 = raw[E + e + 1]; }
        }
    }
    s0 = min(max(s0, 0), n - 1); d0 = min(max(d0, 0), n - 1);
    int p = atomicAdd(&g_pos[d0], 1);
    g_csr[p] = s0;
    if (two) {
        s1 = min(max(s1, 0), n - 1); d1 = min(max(d1, 0), n - 1);
        p = atomicAdd(&g_pos[d1], 1);
        g_csr[p] = s1;
    }
}

// ---------------------------------------------------------------------------
// tf32 tensor-core GEMM: H[n, OUTC] = X[n,128] @ W[128, OUTC]  (X stride 128)
// CTA tile 256x64, 8 warps (4M x 2N), warp tile 64x32, K sliced by 16.
// OutT = float or __half.
// ---------------------------------------------------------------------------
template <int OUTC, typename OutT>
__global__ void __launch_bounds__(256) k_gemm_mma(const float* __restrict__ X,
                                                  const float* __restrict__ W,
                                                  OutT* __restrict__ H, int n) {
    __shared__ float As[32 * 33 * 4];   // 32 groups (block16 x kstep) of 32(+1 pad) float4
    __shared__ float Bs[16 * 33 * 2];   // 16 groups (nsub x kstep) of 32(+1 pad) float2
    const int tid   = threadIdx.x;
    const int lane  = tid & 31;
    const int warp  = tid >> 5;
    const int warpM = warp & 3;
    const int warpN = warp >> 2;
    const int row0  = blockIdx.x * 256;
    const int co    = blockIdx.y * 64;

    float c[4][4][4];
#pragma unroll
    for (int i = 0; i < 4; i++)
#pragma unroll
        for (int j = 0; j < 4; j++)
#pragma unroll
            for (int r = 0; r < 4; r++) c[i][j][r] = 0.f;

    for (int k0 = 0; k0 < 128; k0 += 16) {
#pragma unroll
        for (int f = tid; f < 1024; f += 256) {
            int r  = f >> 2;
            int kq = f & 3;
            int gr = min(row0 + r, n - 1);
            float4 v = *(const float4*)&X[(size_t)gr * 128 + k0 + kq * 4];
            int grp  = (r >> 4) * 2 + (kq >> 1);
            int lb   = (r & 7) * 4;
            int reg  = (kq & 1) * 2 + ((r >> 3) & 1);
            int base = grp * 33 * 4;
            As[(base + (lb + 0) * 4) + reg] = tf32r(v.x);
            As[(base + (lb + 1) * 4) + reg] = tf32r(v.y);
            As[(base + (lb + 2) * 4) + reg] = tf32r(v.z);
            As[(base + (lb + 3) * 4) + reg] = tf32r(v.w);
        }
        {
            int k  = tid >> 4;
            int nq = tid & 15;
            float4 v = *(const float4*)&W[(size_t)(k0 + k) * OUTC + co + nq * 4];
            int kstep = k >> 3, tg = k & 3, regb = (k >> 2) & 1;
            float vv[4] = {v.x, v.y, v.z, v.w};
#pragma unroll
            for (int j = 0; j < 4; j++) {
                int nn = nq * 4 + j;
                int grp = (nn >> 3) * 2 + kstep;
                Bs[(grp * 33 + (nn & 7) * 4 + tg) * 2 + regb] = tf32r(vv[j]);
            }
        }
        __syncthreads();

#pragma unroll
        for (int ks = 0; ks < 2; ks++) {
            uint32_t a[4][4];
            uint32_t b[4][2];
#pragma unroll
            for (int m = 0; m < 4; m++) {
                float4 av = *(const float4*)&As[(((warpM * 4 + m) * 2 + ks) * 33 + lane) * 4];
                a[m][0] = __float_as_uint(av.x);
                a[m][1] = __float_as_uint(av.y);
                a[m][2] = __float_as_uint(av.z);
                a[m][3] = __float_as_uint(av.w);
            }
#pragma unroll
            for (int nb = 0; nb < 4; nb++) {
                float2 bv = *(const float2*)&Bs[(((warpN * 4 + nb) * 2 + ks) * 33 + lane) * 2];
                b[nb][0] = __float_as_uint(bv.x);
                b[nb][1] = __float_as_uint(bv.y);
            }
#pragma unroll
            for (int m = 0; m < 4; m++)
#pragma unroll
                for (int nb = 0; nb < 4; nb++)
                    mma_tf32(c[m][nb], a[m], b[nb]);
        }
        __syncthreads();
    }

    const int g  = lane >> 2;
    const int tg = lane & 3;
#pragma unroll
    for (int m = 0; m < 4; m++) {
#pragma unroll
        for (int nb = 0; nb < 4; nb++) {
            int row = row0 + warpM * 64 + m * 16 + g;
            int col = co + warpN * 32 + nb * 8 + tg * 2;
            if (row < n) {
                if constexpr (sizeof(OutT) == 2)
                    *(__half2*)&H[(size_t)row * OUTC + col] =
                        __floats2half2_rn(c[m][nb][0], c[m][nb][1]);
                else
                    *(float2*)&H[(size_t)row * OUTC + col] =
                        make_float2(c[m][nb][0], c[m][nb][1]);
            }
            if (row + 8 < n) {
                if constexpr (sizeof(OutT) == 2)
                    *(__half2*)&H[(size_t)(row + 8) * OUTC + col] =
                        __floats2half2_rn(c[m][nb][2], c[m][nb][3]);
                else
                    *(float2*)&H[(size_t)(row + 8) * OUTC + col] =
                        make_float2(c[m][nb][2], c[m][nb][3]);
            }
        }
    }
}

// ---------------------------------------------------------------------------
// Aggregation from fp16 source: one warp per dst node, CSR gather, fp32 accum.
// CH=128: lane handles 4 ch (8B load). CH=64: lane handles 2 ch (4B load).
// ---------------------------------------------------------------------------
template <int CH, bool RELU>
__global__ void __launch_bounds__(256) k_agg_h(const __half* __restrict__ H,
                                               float* __restrict__ OUT,
                                               const float* __restrict__ bias,
                                               int n) {
    int node = blockIdx.x * 8 + (threadIdx.x >> 5);
    int lane = threadIdx.x & 31;
    if (node >= n) return;

    float di = g_dinv[node];
    int beg = g_off[node];
    int end = g_off[node + 1];

    if (CH == 128) {
        uint2 rw = *(const uint2*)(H + (size_t)node * 128 + lane * 4);
        float2 p0 = __half22float2(*(__half2*)&rw.x);
        float2 p1 = __half22float2(*(__half2*)&rw.y);
        float ns = di * di;
        float4 acc = make_float4(p0.x * ns, p0.y * ns, p1.x * ns, p1.y * ns);
        int j = beg;
        for (; j + 1 < end; j += 2) {
            int s0 = g_csr[j], s1 = g_csr[j + 1];
            float n0 = g_dinv[s0] * di, n1 = g_dinv[s1] * di;
            uint2 r0 = *(const uint2*)(H + (size_t)s0 * 128 + lane * 4);
            uint2 r1 = *(const uint2*)(H + (size_t)s1 * 128 + lane * 4);
            float2 a0 = __half22float2(*(__half2*)&r0.x);
            float2 a1 = __half22float2(*(__half2*)&r0.y);
            float2 b0 = __half22float2(*(__half2*)&r1.x);
            float2 b1 = __half22float2(*(__half2*)&r1.y);
            acc.x += a0.x * n0 + b0.x * n1;
            acc.y += a0.y * n0 + b0.y * n1;
            acc.z += a1.x * n0 + b1.x * n1;
            acc.w += a1.y * n0 + b1.y * n1;
        }
        if (j < end) {
            int s = g_csr[j];
            float nm = g_dinv[s] * di;
            uint2 r0 = *(const uint2*)(H + (size_t)s * 128 + lane * 4);
            float2 a0 = __half22float2(*(__half2*)&r0.x);
            float2 a1 = __half22float2(*(__half2*)&r0.y);
            acc.x += a0.x * nm; acc.y += a0.y * nm;
            acc.z += a1.x * nm; acc.w += a1.y * nm;
        }
        int cc = lane * 4;
        acc.x += __ldg(&bias[cc]);     acc.y += __ldg(&bias[cc + 1]);
        acc.z += __ldg(&bias[cc + 2]); acc.w += __ldg(&bias[cc + 3]);
        if (RELU) {
            acc.x = fmaxf(acc.x, 0.f); acc.y = fmaxf(acc.y, 0.f);
            acc.z = fmaxf(acc.z, 0.f); acc.w = fmaxf(acc.w, 0.f);
        }
        ((float4*)(OUT + (size_t)node * 128))[lane] = acc;
    } else {
        uint32_t rw = *(const uint32_t*)(H + (size_t)node * 64 + lane * 2);
        float2 p = __half22float2(*(__half2*)&rw);
        float ns = di * di;
        float2 acc = make_float2(p.x * ns, p.y * ns);
        int j = beg;
        for (; j + 1 < end; j += 2) {
            int s0 = g_csr[j], s1 = g_csr[j + 1];
            float n0 = g_dinv[s0] * di, n1 = g_dinv[s1] * di;
            uint32_t r0 = *(const uint32_t*)(H + (size_t)s0 * 64 + lane * 2);
            uint32_t r1 = *(const uint32_t*)(H + (size_t)s1 * 64 + lane * 2);
            float2 a = __half22float2(*(__half2*)&r0);
            float2 b = __half22float2(*(__half2*)&r1);
            acc.x += a.x * n0 + b.x * n1;
            acc.y += a.y * n0 + b.y * n1;
        }
        if (j < end) {
            int s = g_csr[j];
            float nm = g_dinv[s] * di;
            uint32_t r0 = *(const uint32_t*)(H + (size_t)s * 64 + lane * 2);
            float2 a = __half22float2(*(__half2*)&r0);
            acc.x += a.x * nm; acc.y += a.y * nm;
        }
        int cc = lane * 2;
        acc.x += __ldg(&bias[cc]); acc.y += __ldg(&bias[cc + 1]);
        if (RELU) { acc.x = fmaxf(acc.x, 0.f); acc.y = fmaxf(acc.y, 0.f); }
        ((float2*)(OUT + (size_t)node * 64))[lane] = acc;
    }
}

// ---------------------------------------------------------------------------
extern "C" void kernel_launch(void* const* d_in, const int* in_sizes, int n_in,
                              void* d_out, int out_size) {
    const float* x   = (const float*)d_in[0];
    const int*   ei  = (const int*)d_in[1];   // int32 OR int64 (auto-detected)
    const float* W1  = (const float*)d_in[2];
    const float* b1  = (const float*)d_in[3];
    const float* W2  = (const float*)d_in[4];
    const float* b2  = (const float*)d_in[5];
    float*       out = (float*)d_out;

    const int n = in_sizes[0] / 128;
    const int E = in_sizes[1] / 2;

    __half* d_h;  cudaGetSymbolAddress((void**)&d_h,   g_h);
    float* d_agg; cudaGetSymbolAddress((void**)&d_agg, g_agg);
    __half* d_t;  cudaGetSymbolAddress((void**)&d_t,   g_t);

    const int T = 256;

    // Side stream for GEMM1 (independent of CSR build) — fork/join via events.
    cudaStream_t s1;
    cudaStreamCreateWithFlags(&s1, cudaStreamNonBlocking);
    cudaEvent_t e_fork, e_join;
    cudaEventCreateWithFlags(&e_fork, cudaEventDisableTiming);
    cudaEventCreateWithFlags(&e_join, cudaEventDisableTiming);

    cudaEventRecord(e_fork, 0);
    cudaStreamWaitEvent(s1, e_fork, 0);
    {
        dim3 grid((n + 255) / 256, 2);
        k_gemm_mma<128, __half><<<grid, 256, 0, s1>>>(x, W1, d_h, n);
    }
    cudaEventRecord(e_join, s1);

    // CSR build + dinv on the main stream, concurrent with GEMM1
    k_init_detect<<<(n + T - 1) / T, T>>>(ei, E, n);
    {
        int halfE = (E + 1) / 2;
        k_count_f<<<(halfE + T - 1) / T, T>>>(ei, E, n);
    }
    k_scan_block<<<NBLK_SCAN, SCAN_BLK>>>(n);
    k_scan_top<<<1, 64>>>();
    k_scan_add<<<(n + T - 1) / T, T>>>(n, E);
    {
        int halfE = (E + 1) / 2;
        k_fill_f<<<(halfE + T - 1) / T, T>>>(ei, E, n);
    }

    cudaStreamWaitEvent(0, e_join, 0);

    // aggregate layer 1 (fused self-loop + bias + relu), fp16 -> fp32
    k_agg_h<128, true><<<(n + 7) / 8, 256>>>(d_h, d_agg, b1, n);

    // layer 2: t = relu_h @ W2 (fp32 in, fp16 out)
    {
        dim3 grid((n + 255) / 256, 1);
        k_gemm_mma<64, __half><<<grid, 256>>>(d_agg, W2, d_t, n);
    }

    // aggregate layer 2 directly into d_out (fused bias), fp16 -> fp32
    k_agg_h<64, false><<<(n + 7) / 8, 256>>>(d_t, out, b2, n);

    cudaEventDestroy(e_fork);
    cudaEventDestroy(e_join);
    cudaStreamDestroy(s1);
}

// round 9
// speedup vs baseline: 1.5662x; 1.0731x over previous
#include <cuda_runtime.h>
#include <cuda_fp16.h>
#include <stdint.h>

#define N_MAX 50000
#define E_MAX 600000
#define SCAN_BLK 1024
#define NBLK_SCAN ((N_MAX + SCAN_BLK - 1) / SCAN_BLK)   // 49

// Scratch (device globals; no allocation allowed)
__device__ int    g_fmt;                 // 1 = int64 edge_index, 0 = int32
__device__ int    g_cnt[N_MAX];          // zero at entry (static init / re-zeroed each run)
__device__ int    g_off[N_MAX + 1];
__device__ int    g_pos[N_MAX];
__device__ int    g_bsum[NBLK_SCAN + 1];
__device__ float  g_dinv[N_MAX];
__device__ int    g_csr[E_MAX];
__device__ __half g_h[(size_t)N_MAX * 128];   // x @ W1 (fp16 for cheap gather)
__device__ float  g_agg[(size_t)N_MAX * 128]; // aggregated layer-1 (fp32, GEMM2 input)
__device__ __half g_t[(size_t)N_MAX * 64];    // relu_h @ W2 (fp16 for cheap gather)

__device__ __forceinline__ float tf32r(float x) {
    uint32_t u;
    asm("cvt.rna.tf32.f32 %0, %1;" : "=r"(u) : "f"(x));
    return __uint_as_float(u);
}

__device__ __forceinline__ void mma_tf32(float* c, const uint32_t* a, const uint32_t* b) {
    asm volatile(
        "mma.sync.aligned.m16n8k8.row.col.f32.tf32.tf32.f32 "
        "{%0,%1,%2,%3}, {%4,%5,%6,%7}, {%8,%9}, {%0,%1,%2,%3};"
        : "+f"(c[0]), "+f"(c[1]), "+f"(c[2]), "+f"(c[3])
        : "r"(a[0]), "r"(a[1]), "r"(a[2]), "r"(a[3]), "r"(b[0]), "r"(b[1]));
}

// ---------------------------------------------------------------------------
// dtype detection (tiny, 1 block)
// ---------------------------------------------------------------------------
__global__ void k_detect(const int* __restrict__ raw, int E) {
    __shared__ int any_hi;
    if (threadIdx.x == 0) any_hi = 0;
    __syncthreads();
    int samples = E < 4096 ? E : 4096;
    int local = 0;
    for (int i = threadIdx.x; i < samples; i += blockDim.x)
        if (raw[2 * i + 1] != 0) local = 1;   // int64 high words are 0
    if (local) any_hi = 1;
    __syncthreads();
    if (threadIdx.x == 0) g_fmt = (any_hi == 0) ? 1 : 0;
}

// ---------------------------------------------------------------------------
// CSR build: 4 edges per thread (MLP), convert-from-raw fused.
// g_cnt is zero at kernel entry (invariant maintained by k_scan_addtop).
// ---------------------------------------------------------------------------
__global__ void k_count_f(const int* __restrict__ raw, int E, int n) {
    int base = 4 * (blockIdx.x * blockDim.x + threadIdx.x);
    if (base >= E) return;
    int fmt = g_fmt;
    int d[4];
#pragma unroll
    for (int q = 0; q < 4; q++) {
        int e = base + q;
        d[q] = (e < E) ? (fmt ? raw[2 * (E + e)] : raw[E + e]) : -1;
    }
#pragma unroll
    for (int q = 0; q < 4; q++) {
        int e = base + q;
        if (e < E) {
            int dd = min(max(d[q], 0), n - 1);
            atomicAdd(&g_cnt[dd], 1);
        }
    }
}

// per-1024-segment exclusive scan (2-level warp shuffle)
__global__ void __launch_bounds__(SCAN_BLK) k_scan_block(int n) {
    __shared__ int warpsum[32];
    int t = threadIdx.x;
    int i = blockIdx.x * SCAN_BLK + t;
    int v = (i < n) ? g_cnt[i] : 0;
    int lane = t & 31, w = t >> 5;
    int x = v;
#pragma unroll
    for (int d = 1; d < 32; d <<= 1) {
        int y = __shfl_up_sync(0xFFFFFFFFu, x, d);
        if (lane >= d) x += y;
    }
    if (lane == 31) warpsum[w] = x;
    __syncthreads();
    if (w == 0) {
        int s = warpsum[lane];
#pragma unroll
        for (int d = 1; d < 32; d <<= 1) {
            int y = __shfl_up_sync(0xFFFFFFFFu, s, d);
            if (lane >= d) s += y;
        }
        warpsum[lane] = s;
    }
    __syncthreads();
    int base = (w > 0) ? warpsum[w - 1] : 0;
    if (i < n) g_off[i] = base + x - v;         // exclusive within segment
    if (t == SCAN_BLK - 1) g_bsum[blockIdx.x] = base + x;
}

// fused: top-level scan (redundant per block) + add + pos/dinv + cnt re-zero
__global__ void __launch_bounds__(256) k_scan_addtop(int n, int E) {
    __shared__ int part[64];
    __shared__ int sbase;
    int t   = threadIdx.x;
    int seg = (blockIdx.x * 256) >> 10;          // 256 | 1024, so constant per block
    if (t < 64) part[t] = (t < seg && t < NBLK_SCAN) ? g_bsum[t] : 0;
    __syncthreads();
    if (t < 32) {
        int v = part[t] + part[t + 32];
#pragma unroll
        for (int d = 16; d > 0; d >>= 1) v += __shfl_down_sync(0xFFFFFFFFu, v, d);
        if (t == 0) sbase = v;
    }
    __syncthreads();
    int i = blockIdx.x * 256 + t;
    if (i < n) {
        int o = g_off[i] + sbase;
        g_off[i] = o;
        g_pos[i] = o;
        int c = g_cnt[i];
        g_dinv[i] = rsqrtf((float)c + 1.0f);     // +1 self loop
        g_cnt[i] = 0;                            // re-zero for next replay
    }
    if (i == 0) g_off[n] = E;
}

__global__ void k_fill_f(const int* __restrict__ raw, int E, int n) {
    int base = 4 * (blockIdx.x * blockDim.x + threadIdx.x);
    if (base >= E) return;
    int fmt = g_fmt;
    int s[4], d[4];
#pragma unroll
    for (int q = 0; q < 4; q++) {
        int e = base + q;
        if (e < E) {
            s[q] = fmt ? raw[2 * e] : raw[e];
            d[q] = fmt ? raw[2 * (E + e)] : raw[E + e];
        }
    }
#pragma unroll
    for (int q = 0; q < 4; q++) {
        int e = base + q;
        if (e < E) {
            int ss = min(max(s[q], 0), n - 1);
            int dd = min(max(d[q], 0), n - 1);
            int p = atomicAdd(&g_pos[dd], 1);
            g_csr[p] = ss;
        }
    }
}

// ---------------------------------------------------------------------------
// tf32 tensor-core GEMM: H[n, OUTC] = X[n,128] @ W[128, OUTC]  (X stride 128)
// CTA tile 256x64, 8 warps (4M x 2N), warp tile 64x32, K sliced by 16.
// ---------------------------------------------------------------------------
template <int OUTC, typename OutT>
__global__ void __launch_bounds__(256) k_gemm_mma(const float* __restrict__ X,
                                                  const float* __restrict__ W,
                                                  OutT* __restrict__ H, int n) {
    __shared__ float As[32 * 33 * 4];
    __shared__ float Bs[16 * 33 * 2];
    const int tid   = threadIdx.x;
    const int lane  = tid & 31;
    const int warp  = tid >> 5;
    const int warpM = warp & 3;
    const int warpN = warp >> 2;
    const int row0  = blockIdx.x * 256;
    const int co    = blockIdx.y * 64;

    float c[4][4][4];
#pragma unroll
    for (int i = 0; i < 4; i++)
#pragma unroll
        for (int j = 0; j < 4; j++)
#pragma unroll
            for (int r = 0; r < 4; r++) c[i][j][r] = 0.f;

    for (int k0 = 0; k0 < 128; k0 += 16) {
#pragma unroll
        for (int f = tid; f < 1024; f += 256) {
            int r  = f >> 2;
            int kq = f & 3;
            int gr = min(row0 + r, n - 1);
            float4 v = *(const float4*)&X[(size_t)gr * 128 + k0 + kq * 4];
            int grp  = (r >> 4) * 2 + (kq >> 1);
            int lb   = (r & 7) * 4;
            int reg  = (kq & 1) * 2 + ((r >> 3) & 1);
            int base = grp * 33 * 4;
            As[(base + (lb + 0) * 4) + reg] = tf32r(v.x);
            As[(base + (lb + 1) * 4) + reg] = tf32r(v.y);
            As[(base + (lb + 2) * 4) + reg] = tf32r(v.z);
            As[(base + (lb + 3) * 4) + reg] = tf32r(v.w);
        }
        {
            int k  = tid >> 4;
            int nq = tid & 15;
            float4 v = *(const float4*)&W[(size_t)(k0 + k) * OUTC + co + nq * 4];
            int kstep = k >> 3, tg = k & 3, regb = (k >> 2) & 1;
            float vv[4] = {v.x, v.y, v.z, v.w};
#pragma unroll
            for (int j = 0; j < 4; j++) {
                int nn = nq * 4 + j;
                int grp = (nn >> 3) * 2 + kstep;
                Bs[(grp * 33 + (nn & 7) * 4 + tg) * 2 + regb] = tf32r(vv[j]);
            }
        }
        __syncthreads();

#pragma unroll
        for (int ks = 0; ks < 2; ks++) {
            uint32_t a[4][4];
            uint32_t b[4][2];
#pragma unroll
            for (int m = 0; m < 4; m++) {
                float4 av = *(const float4*)&As[(((warpM * 4 + m) * 2 + ks) * 33 + lane) * 4];
                a[m][0] = __float_as_uint(av.x);
                a[m][1] = __float_as_uint(av.y);
                a[m][2] = __float_as_uint(av.z);
                a[m][3] = __float_as_uint(av.w);
            }
#pragma unroll
            for (int nb = 0; nb < 4; nb++) {
                float2 bv = *(const float2*)&Bs[(((warpN * 4 + nb) * 2 + ks) * 33 + lane) * 2];
                b[nb][0] = __float_as_uint(bv.x);
                b[nb][1] = __float_as_uint(bv.y);
            }
#pragma unroll
            for (int m = 0; m < 4; m++)
#pragma unroll
                for (int nb = 0; nb < 4; nb++)
                    mma_tf32(c[m][nb], a[m], b[nb]);
        }
        __syncthreads();
    }

    const int g  = lane >> 2;
    const int tg = lane & 3;
#pragma unroll
    for (int m = 0; m < 4; m++) {
#pragma unroll
        for (int nb = 0; nb < 4; nb++) {
            int row = row0 + warpM * 64 + m * 16 + g;
            int col = co + warpN * 32 + nb * 8 + tg * 2;
            if (row < n) {
                if constexpr (sizeof(OutT) == 2)
                    *(__half2*)&H[(size_t)row * OUTC + col] =
                        __floats2half2_rn(c[m][nb][0], c[m][nb][1]);
                else
                    *(float2*)&H[(size_t)row * OUTC + col] =
                        make_float2(c[m][nb][0], c[m][nb][1]);
            }
            if (row + 8 < n) {
                if constexpr (sizeof(OutT) == 2)
                    *(__half2*)&H[(size_t)(row + 8) * OUTC + col] =
                        __floats2half2_rn(c[m][nb][2], c[m][nb][3]);
                else
                    *(float2*)&H[(size_t)(row + 8) * OUTC + col] =
                        make_float2(c[m][nb][2], c[m][nb][3]);
            }
        }
    }
}

// ---------------------------------------------------------------------------
// Aggregation from fp16 source: one warp per dst node, CSR gather, fp32 accum,
// 4-way unrolled for gather MLP.
// ---------------------------------------------------------------------------
template <int CH, bool RELU>
__global__ void __launch_bounds__(256) k_agg_h(const __half* __restrict__ H,
                                               float* __restrict__ OUT,
                                               const float* __restrict__ bias,
                                               int n) {
    int node = blockIdx.x * 8 + (threadIdx.x >> 5);
    int lane = threadIdx.x & 31;
    if (node >= n) return;

    float di = g_dinv[node];
    int beg = g_off[node];
    int end = g_off[node + 1];

    if (CH == 128) {
        uint2 rw = *(const uint2*)(H + (size_t)node * 128 + lane * 4);
        float2 p0 = __half22float2(*(__half2*)&rw.x);
        float2 p1 = __half22float2(*(__half2*)&rw.y);
        float ns = di * di;
        float4 acc = make_float4(p0.x * ns, p0.y * ns, p1.x * ns, p1.y * ns);
        int j = beg;
        for (; j + 3 < end; j += 4) {
            int   sx[4];
            float nm[4];
            uint2 rv[4];
#pragma unroll
            for (int q = 0; q < 4; q++) sx[q] = g_csr[j + q];
#pragma unroll
            for (int q = 0; q < 4; q++) {
                nm[q] = g_dinv[sx[q]] * di;
                rv[q] = *(const uint2*)(H + (size_t)sx[q] * 128 + lane * 4);
            }
#pragma unroll
            for (int q = 0; q < 4; q++) {
                float2 a0 = __half22float2(*(__half2*)&rv[q].x);
                float2 a1 = __half22float2(*(__half2*)&rv[q].y);
                acc.x += a0.x * nm[q]; acc.y += a0.y * nm[q];
                acc.z += a1.x * nm[q]; acc.w += a1.y * nm[q];
            }
        }
        for (; j < end; j++) {
            int s = g_csr[j];
            float nm = g_dinv[s] * di;
            uint2 r0 = *(const uint2*)(H + (size_t)s * 128 + lane * 4);
            float2 a0 = __half22float2(*(__half2*)&r0.x);
            float2 a1 = __half22float2(*(__half2*)&r0.y);
            acc.x += a0.x * nm; acc.y += a0.y * nm;
            acc.z += a1.x * nm; acc.w += a1.y * nm;
        }
        int cc = lane * 4;
        acc.x += __ldg(&bias[cc]);     acc.y += __ldg(&bias[cc + 1]);
        acc.z += __ldg(&bias[cc + 2]); acc.w += __ldg(&bias[cc + 3]);
        if (RELU) {
            acc.x = fmaxf(acc.x, 0.f); acc.y = fmaxf(acc.y, 0.f);
            acc.z = fmaxf(acc.z, 0.f); acc.w = fmaxf(acc.w, 0.f);
        }
        ((float4*)(OUT + (size_t)node * 128))[lane] = acc;
    } else {
        uint32_t rw = *(const uint32_t*)(H + (size_t)node * 64 + lane * 2);
        float2 p = __half22float2(*(__half2*)&rw);
        float ns = di * di;
        float2 acc = make_float2(p.x * ns, p.y * ns);
        int j = beg;
        for (; j + 3 < end; j += 4) {
            int      sx[4];
            float    nm[4];
            uint32_t rv[4];
#pragma unroll
            for (int q = 0; q < 4; q++) sx[q] = g_csr[j + q];
#pragma unroll
            for (int q = 0; q < 4; q++) {
                nm[q] = g_dinv[sx[q]] * di;
                rv[q] = *(const uint32_t*)(H + (size_t)sx[q] * 64 + lane * 2);
            }
#pragma unroll
            for (int q = 0; q < 4; q++) {
                float2 a = __half22float2(*(__half2*)&rv[q]);
                acc.x += a.x * nm[q]; acc.y += a.y * nm[q];
            }
        }
        for (; j < end; j++) {
            int s = g_csr[j];
            float nm = g_dinv[s] * di;
            uint32_t r0 = *(const uint32_t*)(H + (size_t)s * 64 + lane * 2);
            float2 a = __half22float2(*(__half2*)&r0);
            acc.x += a.x * nm; acc.y += a.y * nm;
        }
        int cc = lane * 2;
        acc.x += __ldg(&bias[cc]); acc.y += __ldg(&bias[cc + 1]);
        if (RELU) { acc.x = fmaxf(acc.x, 0.f); acc.y = fmaxf(acc.y, 0.f); }
        ((float2*)(OUT + (size_t)node * 64))[lane] = acc;
    }
}

// ---------------------------------------------------------------------------
extern "C" void kernel_launch(void* const* d_in, const int* in_sizes, int n_in,
                              void* d_out, int out_size) {
    const float* x   = (const float*)d_in[0];
    const int*   ei  = (const int*)d_in[1];   // int32 OR int64 (auto-detected)
    const float* W1  = (const float*)d_in[2];
    const float* b1  = (const float*)d_in[3];
    const float* W2  = (const float*)d_in[4];
    const float* b2  = (const float*)d_in[5];
    float*       out = (float*)d_out;

    const int n = in_sizes[0] / 128;
    const int E = in_sizes[1] / 2;

    __half* d_h;  cudaGetSymbolAddress((void**)&d_h,   g_h);
    float* d_agg; cudaGetSymbolAddress((void**)&d_agg, g_agg);
    __half* d_t;  cudaGetSymbolAddress((void**)&d_t,   g_t);

    const int T = 256;
    const int quadE = (E + 3) / 4;

    // Side stream for GEMM1 (independent of CSR build) — fork/join via events.
    cudaStream_t s1;
    cudaStreamCreateWithFlags(&s1, cudaStreamNonBlocking);
    cudaEvent_t e_fork, e_join;
    cudaEventCreateWithFlags(&e_fork, cudaEventDisableTiming);
    cudaEventCreateWithFlags(&e_join, cudaEventDisableTiming);

    cudaEventRecord(e_fork, 0);
    cudaStreamWaitEvent(s1, e_fork, 0);
    {
        dim3 grid((n + 255) / 256, 2);
        k_gemm_mma<128, __half><<<grid, 256, 0, s1>>>(x, W1, d_h, n);
    }
    cudaEventRecord(e_join, s1);

    // CSR build + dinv on the main stream, concurrent with GEMM1
    k_detect<<<1, 256>>>(ei, E);
    k_count_f<<<(quadE + T - 1) / T, T>>>(ei, E, n);
    k_scan_block<<<NBLK_SCAN, SCAN_BLK>>>(n);
    k_scan_addtop<<<(n + 255) / 256, 256>>>(n, E);
    k_fill_f<<<(quadE + T - 1) / T, T>>>(ei, E, n);

    cudaStreamWaitEvent(0, e_join, 0);

    // aggregate layer 1 (fused self-loop + bias + relu), fp16 -> fp32
    k_agg_h<128, true><<<(n + 7) / 8, 256>>>(d_h, d_agg, b1, n);

    // layer 2: t = relu_h @ W2 (fp32 in, fp16 out)
    {
        dim3 grid((n + 255) / 256, 1);
        k_gemm_mma<64, __half><<<grid, 256>>>(d_agg, W2, d_t, n);
    }

    // aggregate layer 2 directly into d_out (fused bias), fp16 -> fp32
    k_agg_h<64, false><<<(n + 7) / 8, 256>>>(d_t, out, b2, n);

    cudaEventDestroy(e_fork);
    cudaEventDestroy(e_join);
    cudaStreamDestroy(s1);
}

// round 10
// speedup vs baseline: 1.5713x; 1.0033x over previous
#include <cuda_runtime.h>
#include <cuda_fp16.h>
#include <stdint.h>

#define N_MAX 50000
#define E_MAX 600000
#define SCAN_BLK 1024
#define NBLK_SCAN ((N_MAX + SCAN_BLK - 1) / SCAN_BLK)   // 49

// Scratch (device globals; no allocation allowed)
__device__ int    g_cnt[N_MAX];          // zero at entry (static init / re-zeroed each run)
__device__ int    g_off[N_MAX + 1];
__device__ int    g_pos[N_MAX];
__device__ int    g_bsum[NBLK_SCAN + 1];
__device__ int    g_flag[NBLK_SCAN + 1]; // cleared by k_count_f each run
__device__ float  g_dinv[N_MAX];
__device__ int    g_csr[E_MAX];
__device__ __half g_h[(size_t)N_MAX * 128];   // x @ W1 (fp16 for cheap gather)
__device__ float  g_agg[(size_t)N_MAX * 128]; // aggregated layer-1 (fp32, GEMM2 input)
__device__ __half g_t[(size_t)N_MAX * 64];    // relu_h @ W2 (fp16 for cheap gather)

__device__ __forceinline__ float tf32r(float x) {
    uint32_t u;
    asm("cvt.rna.tf32.f32 %0, %1;" : "=r"(u) : "f"(x));
    return __uint_as_float(u);
}

__device__ __forceinline__ void mma_tf32(float* c, const uint32_t* a, const uint32_t* b) {
    asm volatile(
        "mma.sync.aligned.m16n8k8.row.col.f32.tf32.tf32.f32 "
        "{%0,%1,%2,%3}, {%4,%5,%6,%7}, {%8,%9}, {%0,%1,%2,%3};"
        : "+f"(c[0]), "+f"(c[1]), "+f"(c[2]), "+f"(c[3])
        : "r"(a[0]), "r"(a[1]), "r"(a[2]), "r"(a[3]), "r"(b[0]), "r"(b[1]));
}

// In-block dtype detection: sample 32 odd int32 words. int64 data (values <
// 2^31) has zero hi-words there; int32 random node ids are ~never all zero.
__device__ __forceinline__ int detect_fmt(const int* __restrict__ raw, int E) {
    int idx = 2 * (threadIdx.x & 31) + 1;
    int hw = (idx < 2 * E) ? raw[idx] : 0;
    unsigned any = __ballot_sync(0xFFFFFFFFu, hw != 0);
    return (any == 0) ? 1 : 0;   // 1 = int64, 0 = int32
}

// ---------------------------------------------------------------------------
// count: 4 edges/thread, fused dtype detect + scan-flag clear
// ---------------------------------------------------------------------------
__global__ void k_count_f(const int* __restrict__ raw, int E, int n) {
    __shared__ int s_fmt;
    if (threadIdx.x < 32) {
        int f = detect_fmt(raw, E);
        if (threadIdx.x == 0) s_fmt = f;
    }
    int gid = blockIdx.x * blockDim.x + threadIdx.x;
    if (gid <= NBLK_SCAN) g_flag[gid] = 0;   // clear lookback flags for scan
    __syncthreads();
    int fmt = s_fmt;

    int base = 4 * gid;
    if (base >= E) return;
    int d[4];
#pragma unroll
    for (int q = 0; q < 4; q++) {
        int e = base + q;
        d[q] = (e < E) ? (fmt ? raw[2 * (E + e)] : raw[E + e]) : -1;
    }
#pragma unroll
    for (int q = 0; q < 4; q++) {
        int e = base + q;
        if (e < E) {
            int dd = min(max(d[q], 0), n - 1);
            atomicAdd(&g_cnt[dd], 1);
        }
    }
}

// ---------------------------------------------------------------------------
// single-kernel scan: per-block 2-level shuffle scan + decoupled lookback
// (49 blocks, all resident), then offsets/pos/dinv + cnt re-zero.
// ---------------------------------------------------------------------------
__global__ void __launch_bounds__(SCAN_BLK) k_scan(int n, int E) {
    __shared__ int warpsum[32];
    __shared__ int pred[2];
    const int b = blockIdx.x;
    const int t = threadIdx.x;
    const int i = b * SCAN_BLK + t;
    const int v = (i < n) ? g_cnt[i] : 0;
    const int lane = t & 31, w = t >> 5;

    // local inclusive scan
    int x = v;
#pragma unroll
    for (int d = 1; d < 32; d <<= 1) {
        int y = __shfl_up_sync(0xFFFFFFFFu, x, d);
        if (lane >= d) x += y;
    }
    if (lane == 31) warpsum[w] = x;
    __syncthreads();
    if (w == 0) {
        int s = warpsum[lane];
#pragma unroll
        for (int d = 1; d < 32; d <<= 1) {
            int y = __shfl_up_sync(0xFFFFFFFFu, s, d);
            if (lane >= d) s += y;
        }
        warpsum[lane] = s;
    }
    __syncthreads();
    const int base  = (w > 0) ? warpsum[w - 1] : 0;
    const int total = warpsum[31];

    // publish block aggregate
    if (t == 0) {
        g_bsum[b] = total;
        __threadfence();
        ((volatile int*)g_flag)[b] = 1;
    }

    // lookback: threads t < b poll predecessor flags (b <= 48)
    int pv = 0;
    if (t < b) {
        while (((volatile int*)g_flag)[t] == 0) {}
        __threadfence();
        pv = g_bsum[t];
    }
    if (t < 64) {
        int s = pv;
#pragma unroll
        for (int d = 16; d > 0; d >>= 1) s += __shfl_down_sync(0xFFFFFFFFu, s, d);
        if (lane == 0) pred[w] = s;
    }
    __syncthreads();
    const int prefix = pred[0] + pred[1];

    if (i < n) {
        int o = prefix + base + x - v;           // global exclusive
        g_off[i] = o;
        g_pos[i] = o;
        g_dinv[i] = rsqrtf((float)v + 1.0f);     // +1 self loop
        g_cnt[i] = 0;                            // re-zero for next replay
    }
    if (b == 0 && t == 0) g_off[n] = E;
}

// ---------------------------------------------------------------------------
// fill: 4 edges/thread, fused dtype detect
// ---------------------------------------------------------------------------
__global__ void k_fill_f(const int* __restrict__ raw, int E, int n) {
    __shared__ int s_fmt;
    if (threadIdx.x < 32) {
        int f = detect_fmt(raw, E);
        if (threadIdx.x == 0) s_fmt = f;
    }
    __syncthreads();
    int fmt = s_fmt;

    int base = 4 * (blockIdx.x * blockDim.x + threadIdx.x);
    if (base >= E) return;
    int s[4], d[4];
#pragma unroll
    for (int q = 0; q < 4; q++) {
        int e = base + q;
        if (e < E) {
            s[q] = fmt ? raw[2 * e] : raw[e];
            d[q] = fmt ? raw[2 * (E + e)] : raw[E + e];
        }
    }
#pragma unroll
    for (int q = 0; q < 4; q++) {
        int e = base + q;
        if (e < E) {
            int ss = min(max(s[q], 0), n - 1);
            int dd = min(max(d[q], 0), n - 1);
            int p = atomicAdd(&g_pos[dd], 1);
            g_csr[p] = ss;
        }
    }
}

// ---------------------------------------------------------------------------
// tf32 tensor-core GEMM: H[n, OUTC] = X[n,128] @ W[128, OUTC]  (X stride 128)
// CTA tile 256x64, 8 warps (4M x 2N), warp tile 64x32, K sliced by 16.
// ---------------------------------------------------------------------------
template <int OUTC, typename OutT>
__global__ void __launch_bounds__(256) k_gemm_mma(const float* __restrict__ X,
                                                  const float* __restrict__ W,
                                                  OutT* __restrict__ H, int n) {
    __shared__ float As[32 * 33 * 4];
    __shared__ float Bs[16 * 33 * 2];
    const int tid   = threadIdx.x;
    const int lane  = tid & 31;
    const int warp  = tid >> 5;
    const int warpM = warp & 3;
    const int warpN = warp >> 2;
    const int row0  = blockIdx.x * 256;
    const int co    = blockIdx.y * 64;

    float c[4][4][4];
#pragma unroll
    for (int i = 0; i < 4; i++)
#pragma unroll
        for (int j = 0; j < 4; j++)
#pragma unroll
            for (int r = 0; r < 4; r++) c[i][j][r] = 0.f;

    for (int k0 = 0; k0 < 128; k0 += 16) {
#pragma unroll
        for (int f = tid; f < 1024; f += 256) {
            int r  = f >> 2;
            int kq = f & 3;
            int gr = min(row0 + r, n - 1);
            float4 v = *(const float4*)&X[(size_t)gr * 128 + k0 + kq * 4];
            int grp  = (r >> 4) * 2 + (kq >> 1);
            int lb   = (r & 7) * 4;
            int reg  = (kq & 1) * 2 + ((r >> 3) & 1);
            int sbase = grp * 33 * 4;
            As[(sbase + (lb + 0) * 4) + reg] = tf32r(v.x);
            As[(sbase + (lb + 1) * 4) + reg] = tf32r(v.y);
            As[(sbase + (lb + 2) * 4) + reg] = tf32r(v.z);
            As[(sbase + (lb + 3) * 4) + reg] = tf32r(v.w);
        }
        {
            int k  = tid >> 4;
            int nq = tid & 15;
            float4 v = *(const float4*)&W[(size_t)(k0 + k) * OUTC + co + nq * 4];
            int kstep = k >> 3, tg = k & 3, regb = (k >> 2) & 1;
            float vv[4] = {v.x, v.y, v.z, v.w};
#pragma unroll
            for (int j = 0; j < 4; j++) {
                int nn = nq * 4 + j;
                int grp = (nn >> 3) * 2 + kstep;
                Bs[(grp * 33 + (nn & 7) * 4 + tg) * 2 + regb] = tf32r(vv[j]);
            }
        }
        __syncthreads();

#pragma unroll
        for (int ks = 0; ks < 2; ks++) {
            uint32_t a[4][4];
            uint32_t b[4][2];
#pragma unroll
            for (int m = 0; m < 4; m++) {
                float4 av = *(const float4*)&As[(((warpM * 4 + m) * 2 + ks) * 33 + lane) * 4];
                a[m][0] = __float_as_uint(av.x);
                a[m][1] = __float_as_uint(av.y);
                a[m][2] = __float_as_uint(av.z);
                a[m][3] = __float_as_uint(av.w);
            }
#pragma unroll
            for (int nb = 0; nb < 4; nb++) {
                float2 bv = *(const float2*)&Bs[(((warpN * 4 + nb) * 2 + ks) * 33 + lane) * 2];
                b[nb][0] = __float_as_uint(bv.x);
                b[nb][1] = __float_as_uint(bv.y);
            }
#pragma unroll
            for (int m = 0; m < 4; m++)
#pragma unroll
                for (int nb = 0; nb < 4; nb++)
                    mma_tf32(c[m][nb], a[m], b[nb]);
        }
        __syncthreads();
    }

    const int g  = lane >> 2;
    const int tg = lane & 3;
#pragma unroll
    for (int m = 0; m < 4; m++) {
#pragma unroll
        for (int nb = 0; nb < 4; nb++) {
            int row = row0 + warpM * 64 + m * 16 + g;
            int col = co + warpN * 32 + nb * 8 + tg * 2;
            if (row < n) {
                if constexpr (sizeof(OutT) == 2)
                    *(__half2*)&H[(size_t)row * OUTC + col] =
                        __floats2half2_rn(c[m][nb][0], c[m][nb][1]);
                else
                    *(float2*)&H[(size_t)row * OUTC + col] =
                        make_float2(c[m][nb][0], c[m][nb][1]);
            }
            if (row + 8 < n) {
                if constexpr (sizeof(OutT) == 2)
                    *(__half2*)&H[(size_t)(row + 8) * OUTC + col] =
                        __floats2half2_rn(c[m][nb][2], c[m][nb][3]);
                else
                    *(float2*)&H[(size_t)(row + 8) * OUTC + col] =
                        make_float2(c[m][nb][2], c[m][nb][3]);
            }
        }
    }
}

// ---------------------------------------------------------------------------
// Aggregation from fp16 source: one warp per dst node, CSR gather, fp32 accum,
// 4-way unrolled for gather MLP.
// ---------------------------------------------------------------------------
template <int CH, bool RELU>
__global__ void __launch_bounds__(256) k_agg_h(const __half* __restrict__ H,
                                               float* __restrict__ OUT,
                                               const float* __restrict__ bias,
                                               int n) {
    int node = blockIdx.x * 8 + (threadIdx.x >> 5);
    int lane = threadIdx.x & 31;
    if (node >= n) return;

    float di = g_dinv[node];
    int beg = g_off[node];
    int end = g_off[node + 1];

    if (CH == 128) {
        uint2 rw = *(const uint2*)(H + (size_t)node * 128 + lane * 4);
        float2 p0 = __half22float2(*(__half2*)&rw.x);
        float2 p1 = __half22float2(*(__half2*)&rw.y);
        float ns = di * di;
        float4 acc = make_float4(p0.x * ns, p0.y * ns, p1.x * ns, p1.y * ns);
        int j = beg;
        for (; j + 3 < end; j += 4) {
            int   sx[4];
            float nm[4];
            uint2 rv[4];
#pragma unroll
            for (int q = 0; q < 4; q++) sx[q] = g_csr[j + q];
#pragma unroll
            for (int q = 0; q < 4; q++) {
                nm[q] = g_dinv[sx[q]] * di;
                rv[q] = *(const uint2*)(H + (size_t)sx[q] * 128 + lane * 4);
            }
#pragma unroll
            for (int q = 0; q < 4; q++) {
                float2 a0 = __half22float2(*(__half2*)&rv[q].x);
                float2 a1 = __half22float2(*(__half2*)&rv[q].y);
                acc.x += a0.x * nm[q]; acc.y += a0.y * nm[q];
                acc.z += a1.x * nm[q]; acc.w += a1.y * nm[q];
            }
        }
        for (; j < end; j++) {
            int s = g_csr[j];
            float nm = g_dinv[s] * di;
            uint2 r0 = *(const uint2*)(H + (size_t)s * 128 + lane * 4);
            float2 a0 = __half22float2(*(__half2*)&r0.x);
            float2 a1 = __half22float2(*(__half2*)&r0.y);
            acc.x += a0.x * nm; acc.y += a0.y * nm;
            acc.z += a1.x * nm; acc.w += a1.y * nm;
        }
        int cc = lane * 4;
        acc.x += __ldg(&bias[cc]);     acc.y += __ldg(&bias[cc + 1]);
        acc.z += __ldg(&bias[cc + 2]); acc.w += __ldg(&bias[cc + 3]);
        if (RELU) {
            acc.x = fmaxf(acc.x, 0.f); acc.y = fmaxf(acc.y, 0.f);
            acc.z = fmaxf(acc.z, 0.f); acc.w = fmaxf(acc.w, 0.f);
        }
        ((float4*)(OUT + (size_t)node * 128))[lane] = acc;
    } else {
        uint32_t rw = *(const uint32_t*)(H + (size_t)node * 64 + lane * 2);
        float2 p = __half22float2(*(__half2*)&rw);
        float ns = di * di;
        float2 acc = make_float2(p.x * ns, p.y * ns);
        int j = beg;
        for (; j + 3 < end; j += 4) {
            int      sx[4];
            float    nm[4];
            uint32_t rv[4];
#pragma unroll
            for (int q = 0; q < 4; q++) sx[q] = g_csr[j + q];
#pragma unroll
            for (int q = 0; q < 4; q++) {
                nm[q] = g_dinv[sx[q]] * di;
                rv[q] = *(const uint32_t*)(H + (size_t)sx[q] * 64 + lane * 2);
            }
#pragma unroll
            for (int q = 0; q < 4; q++) {
                float2 a = __half22float2(*(__half2*)&rv[q]);
                acc.x += a.x * nm[q]; acc.y += a.y * nm[q];
            }
        }
        for (; j < end; j++) {
            int s = g_csr[j];
            float nm = g_dinv[s] * di;
            uint32_t r0 = *(const uint32_t*)(H + (size_t)s * 64 + lane * 2);
            float2 a = __half22float2(*(__half2*)&r0);
            acc.x += a.x * nm; acc.y += a.y * nm;
        }
        int cc = lane * 2;
        acc.x += __ldg(&bias[cc]); acc.y += __ldg(&bias[cc + 1]);
        if (RELU) { acc.x = fmaxf(acc.x, 0.f); acc.y = fmaxf(acc.y, 0.f); }
        ((float2*)(OUT + (size_t)node * 64))[lane] = acc;
    }
}

// ---------------------------------------------------------------------------
extern "C" void kernel_launch(void* const* d_in, const int* in_sizes, int n_in,
                              void* d_out, int out_size) {
    const float* x   = (const float*)d_in[0];
    const int*   ei  = (const int*)d_in[1];   // int32 OR int64 (auto-detected)
    const float* W1  = (const float*)d_in[2];
    const float* b1  = (const float*)d_in[3];
    const float* W2  = (const float*)d_in[4];
    const float* b2  = (const float*)d_in[5];
    float*       out = (float*)d_out;

    const int n = in_sizes[0] / 128;
    const int E = in_sizes[1] / 2;

    __half* d_h;  cudaGetSymbolAddress((void**)&d_h,   g_h);
    float* d_agg; cudaGetSymbolAddress((void**)&d_agg, g_agg);
    __half* d_t;  cudaGetSymbolAddress((void**)&d_t,   g_t);

    const int T = 256;
    const int quadE = (E + 3) / 4;

    // Side stream for GEMM1 (independent of CSR build) — fork/join via events.
    cudaStream_t s1;
    cudaStreamCreateWithFlags(&s1, cudaStreamNonBlocking);
    cudaEvent_t e_fork, e_join;
    cudaEventCreateWithFlags(&e_fork, cudaEventDisableTiming);
    cudaEventCreateWithFlags(&e_join, cudaEventDisableTiming);

    cudaEventRecord(e_fork, 0);
    cudaStreamWaitEvent(s1, e_fork, 0);
    {
        dim3 grid((n + 255) / 256, 2);
        k_gemm_mma<128, __half><<<grid, 256, 0, s1>>>(x, W1, d_h, n);
    }
    cudaEventRecord(e_join, s1);

    // CSR build + dinv on the main stream, concurrent with GEMM1 (3 kernels)
    k_count_f<<<(quadE + T - 1) / T, T>>>(ei, E, n);
    k_scan<<<NBLK_SCAN, SCAN_BLK>>>(n, E);
    k_fill_f<<<(quadE + T - 1) / T, T>>>(ei, E, n);

    cudaStreamWaitEvent(0, e_join, 0);

    // aggregate layer 1 (fused self-loop + bias + relu), fp16 -> fp32
    k_agg_h<128, true><<<(n + 7) / 8, 256>>>(d_h, d_agg, b1, n);

    // layer 2: t = relu_h @ W2 (fp32 in, fp16 out)
    {
        dim3 grid((n + 255) / 256, 1);
        k_gemm_mma<64, __half><<<grid, 256>>>(d_agg, W2, d_t, n);
    }

    // aggregate layer 2 directly into d_out (fused bias), fp16 -> fp32
    k_agg_h<64, false><<<(n + 7) / 8, 256>>>(d_t, out, b2, n);

    cudaEventDestroy(e_fork);
    cudaEventDestroy(e_join);
    cudaStreamDestroy(s1);
}

// round 11
// speedup vs baseline: 1.6177x; 1.0295x over previous
#include <cuda_runtime.h>
#include <cuda_fp16.h>
#include <stdint.h>

#define N_MAX 50000
#define E_MAX 600000
#define SCAN_BLK 1024
#define NBLK_SCAN ((N_MAX + SCAN_BLK - 1) / SCAN_BLK)   // 49

// Scratch (device globals; no allocation allowed)
__device__ int    g_cnt[N_MAX];          // zero at entry (static init / re-zeroed each run)
__device__ int    g_off[N_MAX + 1];
__device__ int    g_pos[N_MAX];
__device__ int    g_bsum[NBLK_SCAN + 1];
__device__ int    g_flag[NBLK_SCAN + 1]; // cleared by k_count_f each run
__device__ float  g_dinv[N_MAX];
__device__ int    g_csr[E_MAX];
__device__ __half g_h[(size_t)N_MAX * 128];   // x @ W1 (fp16)
__device__ __half g_agg[(size_t)N_MAX * 128]; // aggregated layer-1 (fp16, GEMM2 input)
__device__ __half g_t[(size_t)N_MAX * 64];    // relu_h @ W2 (fp16)

__device__ __forceinline__ float tf32r(float x) {
    uint32_t u;
    asm("cvt.rna.tf32.f32 %0, %1;" : "=r"(u) : "f"(x));
    return __uint_as_float(u);
}

__device__ __forceinline__ void mma_tf32(float* c, const uint32_t* a, const uint32_t* b) {
    asm volatile(
        "mma.sync.aligned.m16n8k8.row.col.f32.tf32.tf32.f32 "
        "{%0,%1,%2,%3}, {%4,%5,%6,%7}, {%8,%9}, {%0,%1,%2,%3};"
        : "+f"(c[0]), "+f"(c[1]), "+f"(c[2]), "+f"(c[3])
        : "r"(a[0]), "r"(a[1]), "r"(a[2]), "r"(a[3]), "r"(b[0]), "r"(b[1]));
}

// In-block dtype detection: sample 32 odd int32 words. int64 data (values <
// 2^31) has zero hi-words there; int32 random node ids are ~never all zero.
__device__ __forceinline__ int detect_fmt(const int* __restrict__ raw, int E) {
    int idx = 2 * (threadIdx.x & 31) + 1;
    int hw = (idx < 2 * E) ? raw[idx] : 0;
    unsigned any = __ballot_sync(0xFFFFFFFFu, hw != 0);
    return (any == 0) ? 1 : 0;   // 1 = int64, 0 = int32
}

// ---------------------------------------------------------------------------
// count: 2 edges/thread (full occupancy), fused dtype detect + flag clear
// ---------------------------------------------------------------------------
__global__ void k_count_f(const int* __restrict__ raw, int E, int n) {
    __shared__ int s_fmt;
    if (threadIdx.x < 32) {
        int f = detect_fmt(raw, E);
        if (threadIdx.x == 0) s_fmt = f;
    }
    int gid = blockIdx.x * blockDim.x + threadIdx.x;
    if (gid <= NBLK_SCAN) g_flag[gid] = 0;   // clear lookback flags for scan
    __syncthreads();
    int fmt = s_fmt;

    int base = 2 * gid;
    if (base >= E) return;
    int d0 = fmt ? raw[2 * (E + base)] : raw[E + base];
    int e1 = base + 1;
    int d1 = (e1 < E) ? (fmt ? raw[2 * (E + e1)] : raw[E + e1]) : -1;
    atomicAdd(&g_cnt[min(max(d0, 0), n - 1)], 1);
    if (e1 < E) atomicAdd(&g_cnt[min(max(d1, 0), n - 1)], 1);
}

// ---------------------------------------------------------------------------
// single-kernel scan: per-block 2-level shuffle scan + decoupled lookback
// (49 blocks, all resident), then offsets/pos/dinv + cnt re-zero.
// ---------------------------------------------------------------------------
__global__ void __launch_bounds__(SCAN_BLK) k_scan(int n, int E) {
    __shared__ int warpsum[32];
    __shared__ int pred[2];
    const int b = blockIdx.x;
    const int t = threadIdx.x;
    const int i = b * SCAN_BLK + t;
    const int v = (i < n) ? g_cnt[i] : 0;
    const int lane = t & 31, w = t >> 5;

    int x = v;
#pragma unroll
    for (int d = 1; d < 32; d <<= 1) {
        int y = __shfl_up_sync(0xFFFFFFFFu, x, d);
        if (lane >= d) x += y;
    }
    if (lane == 31) warpsum[w] = x;
    __syncthreads();
    if (w == 0) {
        int s = warpsum[lane];
#pragma unroll
        for (int d = 1; d < 32; d <<= 1) {
            int y = __shfl_up_sync(0xFFFFFFFFu, s, d);
            if (lane >= d) s += y;
        }
        warpsum[lane] = s;
    }
    __syncthreads();
    const int base  = (w > 0) ? warpsum[w - 1] : 0;
    const int total = warpsum[31];

    if (t == 0) {
        g_bsum[b] = total;
        __threadfence();
        ((volatile int*)g_flag)[b] = 1;
    }

    int pv = 0;
    if (t < b) {
        while (((volatile int*)g_flag)[t] == 0) {}
        __threadfence();
        pv = g_bsum[t];
    }
    if (t < 64) {
        int s = pv;
#pragma unroll
        for (int d = 16; d > 0; d >>= 1) s += __shfl_down_sync(0xFFFFFFFFu, s, d);
        if (lane == 0) pred[w] = s;
    }
    __syncthreads();
    const int prefix = pred[0] + pred[1];

    if (i < n) {
        int o = prefix + base + x - v;           // global exclusive
        g_off[i] = o;
        g_pos[i] = o;
        g_dinv[i] = rsqrtf((float)v + 1.0f);     // +1 self loop
        g_cnt[i] = 0;                            // re-zero for next replay
    }
    if (b == 0 && t == 0) g_off[n] = E;
}

// ---------------------------------------------------------------------------
// fill: 2 edges/thread (full occupancy), fused dtype detect
// ---------------------------------------------------------------------------
__global__ void k_fill_f(const int* __restrict__ raw, int E, int n) {
    __shared__ int s_fmt;
    if (threadIdx.x < 32) {
        int f = detect_fmt(raw, E);
        if (threadIdx.x == 0) s_fmt = f;
    }
    __syncthreads();
    int fmt = s_fmt;

    int base = 2 * (blockIdx.x * blockDim.x + threadIdx.x);
    if (base >= E) return;
    int s0 = fmt ? raw[2 * base] : raw[base];
    int d0 = fmt ? raw[2 * (E + base)] : raw[E + base];
    int e1 = base + 1;
    int s1 = 0, d1 = 0;
    if (e1 < E) {
        s1 = fmt ? raw[2 * e1] : raw[e1];
        d1 = fmt ? raw[2 * (E + e1)] : raw[E + e1];
    }
    int p0 = atomicAdd(&g_pos[min(max(d0, 0), n - 1)], 1);
    g_csr[p0] = min(max(s0, 0), n - 1);
    if (e1 < E) {
        int p1 = atomicAdd(&g_pos[min(max(d1, 0), n - 1)], 1);
        g_csr[p1] = min(max(s1, 0), n - 1);
    }
}

// ---------------------------------------------------------------------------
// tf32 tensor-core GEMM: H[n, OUTC] = X[n,128] @ W[128, OUTC]
// InT/OutT = float or __half. CTA tile 256x64, 8 warps, K sliced by 16.
// ---------------------------------------------------------------------------
template <int OUTC, typename InT, typename OutT>
__global__ void __launch_bounds__(256) k_gemm_mma(const InT* __restrict__ X,
                                                  const float* __restrict__ W,
                                                  OutT* __restrict__ H, int n) {
    __shared__ float As[32 * 33 * 4];
    __shared__ float Bs[16 * 33 * 2];
    const int tid   = threadIdx.x;
    const int lane  = tid & 31;
    const int warp  = tid >> 5;
    const int warpM = warp & 3;
    const int warpN = warp >> 2;
    const int row0  = blockIdx.x * 256;
    const int co    = blockIdx.y * 64;

    float c[4][4][4];
#pragma unroll
    for (int i = 0; i < 4; i++)
#pragma unroll
        for (int j = 0; j < 4; j++)
#pragma unroll
            for (int r = 0; r < 4; r++) c[i][j][r] = 0.f;

    for (int k0 = 0; k0 < 128; k0 += 16) {
#pragma unroll
        for (int f = tid; f < 1024; f += 256) {
            int r  = f >> 2;
            int kq = f & 3;
            int gr = min(row0 + r, n - 1);
            float4 v;
            if constexpr (sizeof(InT) == 2) {
                uint2 hv = *(const uint2*)&X[(size_t)gr * 128 + k0 + kq * 4];
                float2 f0 = __half22float2(*(__half2*)&hv.x);
                float2 f1 = __half22float2(*(__half2*)&hv.y);
                v = make_float4(f0.x, f0.y, f1.x, f1.y);
            } else {
                v = *(const float4*)&X[(size_t)gr * 128 + k0 + kq * 4];
            }
            int grp  = (r >> 4) * 2 + (kq >> 1);
            int lb   = (r & 7) * 4;
            int reg  = (kq & 1) * 2 + ((r >> 3) & 1);
            int sbase = grp * 33 * 4;
            As[(sbase + (lb + 0) * 4) + reg] = tf32r(v.x);
            As[(sbase + (lb + 1) * 4) + reg] = tf32r(v.y);
            As[(sbase + (lb + 2) * 4) + reg] = tf32r(v.z);
            As[(sbase + (lb + 3) * 4) + reg] = tf32r(v.w);
        }
        {
            int k  = tid >> 4;
            int nq = tid & 15;
            float4 v = *(const float4*)&W[(size_t)(k0 + k) * OUTC + co + nq * 4];
            int kstep = k >> 3, tg = k & 3, regb = (k >> 2) & 1;
            float vv[4] = {v.x, v.y, v.z, v.w};
#pragma unroll
            for (int j = 0; j < 4; j++) {
                int nn = nq * 4 + j;
                int grp = (nn >> 3) * 2 + kstep;
                Bs[(grp * 33 + (nn & 7) * 4 + tg) * 2 + regb] = tf32r(vv[j]);
            }
        }
        __syncthreads();

#pragma unroll
        for (int ks = 0; ks < 2; ks++) {
            uint32_t a[4][4];
            uint32_t b[4][2];
#pragma unroll
            for (int m = 0; m < 4; m++) {
                float4 av = *(const float4*)&As[(((warpM * 4 + m) * 2 + ks) * 33 + lane) * 4];
                a[m][0] = __float_as_uint(av.x);
                a[m][1] = __float_as_uint(av.y);
                a[m][2] = __float_as_uint(av.z);
                a[m][3] = __float_as_uint(av.w);
            }
#pragma unroll
            for (int nb = 0; nb < 4; nb++) {
                float2 bv = *(const float2*)&Bs[(((warpN * 4 + nb) * 2 + ks) * 33 + lane) * 2];
                b[nb][0] = __float_as_uint(bv.x);
                b[nb][1] = __float_as_uint(bv.y);
            }
#pragma unroll
            for (int m = 0; m < 4; m++)
#pragma unroll
                for (int nb = 0; nb < 4; nb++)
                    mma_tf32(c[m][nb], a[m], b[nb]);
        }
        __syncthreads();
    }

    const int g  = lane >> 2;
    const int tg = lane & 3;
#pragma unroll
    for (int m = 0; m < 4; m++) {
#pragma unroll
        for (int nb = 0; nb < 4; nb++) {
            int row = row0 + warpM * 64 + m * 16 + g;
            int col = co + warpN * 32 + nb * 8 + tg * 2;
            if (row < n) {
                if constexpr (sizeof(OutT) == 2)
                    *(__half2*)&H[(size_t)row * OUTC + col] =
                        __floats2half2_rn(c[m][nb][0], c[m][nb][1]);
                else
                    *(float2*)&H[(size_t)row * OUTC + col] =
                        make_float2(c[m][nb][0], c[m][nb][1]);
            }
            if (row + 8 < n) {
                if constexpr (sizeof(OutT) == 2)
                    *(__half2*)&H[(size_t)(row + 8) * OUTC + col] =
                        __floats2half2_rn(c[m][nb][2], c[m][nb][3]);
                else
                    *(float2*)&H[(size_t)(row + 8) * OUTC + col] =
                        make_float2(c[m][nb][2], c[m][nb][3]);
            }
        }
    }
}

// ---------------------------------------------------------------------------
// Aggregation from fp16 source: one warp per dst node, CSR gather, fp32 accum,
// 4-way unrolled for gather MLP. OutT = float or __half.
// ---------------------------------------------------------------------------
template <int CH, bool RELU, typename OutT>
__global__ void __launch_bounds__(256) k_agg_h(const __half* __restrict__ H,
                                               OutT* __restrict__ OUT,
                                               const float* __restrict__ bias,
                                               int n) {
    int node = blockIdx.x * 8 + (threadIdx.x >> 5);
    int lane = threadIdx.x & 31;
    if (node >= n) return;

    float di = g_dinv[node];
    int beg = g_off[node];
    int end = g_off[node + 1];

    if (CH == 128) {
        uint2 rw = *(const uint2*)(H + (size_t)node * 128 + lane * 4);
        float2 p0 = __half22float2(*(__half2*)&rw.x);
        float2 p1 = __half22float2(*(__half2*)&rw.y);
        float ns = di * di;
        float4 acc = make_float4(p0.x * ns, p0.y * ns, p1.x * ns, p1.y * ns);
        int j = beg;
        for (; j + 3 < end; j += 4) {
            int   sx[4];
            float nm[4];
            uint2 rv[4];
#pragma unroll
            for (int q = 0; q < 4; q++) sx[q] = g_csr[j + q];
#pragma unroll
            for (int q = 0; q < 4; q++) {
                nm[q] = g_dinv[sx[q]] * di;
                rv[q] = *(const uint2*)(H + (size_t)sx[q] * 128 + lane * 4);
            }
#pragma unroll
            for (int q = 0; q < 4; q++) {
                float2 a0 = __half22float2(*(__half2*)&rv[q].x);
                float2 a1 = __half22float2(*(__half2*)&rv[q].y);
                acc.x += a0.x * nm[q]; acc.y += a0.y * nm[q];
                acc.z += a1.x * nm[q]; acc.w += a1.y * nm[q];
            }
        }
        for (; j < end; j++) {
            int s = g_csr[j];
            float nm = g_dinv[s] * di;
            uint2 r0 = *(const uint2*)(H + (size_t)s * 128 + lane * 4);
            float2 a0 = __half22float2(*(__half2*)&r0.x);
            float2 a1 = __half22float2(*(__half2*)&r0.y);
            acc.x += a0.x * nm; acc.y += a0.y * nm;
            acc.z += a1.x * nm; acc.w += a1.y * nm;
        }
        int cc = lane * 4;
        acc.x += __ldg(&bias[cc]);     acc.y += __ldg(&bias[cc + 1]);
        acc.z += __ldg(&bias[cc + 2]); acc.w += __ldg(&bias[cc + 3]);
        if (RELU) {
            acc.x = fmaxf(acc.x, 0.f); acc.y = fmaxf(acc.y, 0.f);
            acc.z = fmaxf(acc.z, 0.f); acc.w = fmaxf(acc.w, 0.f);
        }
        if constexpr (sizeof(OutT) == 2) {
            uint2 o;
            *(__half2*)&o.x = __floats2half2_rn(acc.x, acc.y);
            *(__half2*)&o.y = __floats2half2_rn(acc.z, acc.w);
            *(uint2*)(OUT + (size_t)node * 128 + lane * 4) = o;
        } else {
            ((float4*)(OUT + (size_t)node * 128))[lane] = acc;
        }
    } else {
        uint32_t rw = *(const uint32_t*)(H + (size_t)node * 64 + lane * 2);
        float2 p = __half22float2(*(__half2*)&rw);
        float ns = di * di;
        float2 acc = make_float2(p.x * ns, p.y * ns);
        int j = beg;
        for (; j + 3 < end; j += 4) {
            int      sx[4];
            float    nm[4];
            uint32_t rv[4];
#pragma unroll
            for (int q = 0; q < 4; q++) sx[q] = g_csr[j + q];
#pragma unroll
            for (int q = 0; q < 4; q++) {
                nm[q] = g_dinv[sx[q]] * di;
                rv[q] = *(const uint32_t*)(H + (size_t)sx[q] * 64 + lane * 2);
            }
#pragma unroll
            for (int q = 0; q < 4; q++) {
                float2 a = __half22float2(*(__half2*)&rv[q]);
                acc.x += a.x * nm[q]; acc.y += a.y * nm[q];
            }
        }
        for (; j < end; j++) {
            int s = g_csr[j];
            float nm = g_dinv[s] * di;
            uint32_t r0 = *(const uint32_t*)(H + (size_t)s * 64 + lane * 2);
            float2 a = __half22float2(*(__half2*)&r0);
            acc.x += a.x * nm; acc.y += a.y * nm;
        }
        int cc = lane * 2;
        acc.x += __ldg(&bias[cc]); acc.y += __ldg(&bias[cc + 1]);
        if (RELU) { acc.x = fmaxf(acc.x, 0.f); acc.y = fmaxf(acc.y, 0.f); }
        if constexpr (sizeof(OutT) == 2) {
            *(__half2*)(OUT + (size_t)node * 64 + lane * 2) =
                __floats2half2_rn(acc.x, acc.y);
        } else {
            ((float2*)(OUT + (size_t)node * 64))[lane] = acc;
        }
    }
}

// ---------------------------------------------------------------------------
extern "C" void kernel_launch(void* const* d_in, const int* in_sizes, int n_in,
                              void* d_out, int out_size) {
    const float* x   = (const float*)d_in[0];
    const int*   ei  = (const int*)d_in[1];   // int32 OR int64 (auto-detected)
    const float* W1  = (const float*)d_in[2];
    const float* b1  = (const float*)d_in[3];
    const float* W2  = (const float*)d_in[4];
    const float* b2  = (const float*)d_in[5];
    float*       out = (float*)d_out;

    const int n = in_sizes[0] / 128;
    const int E = in_sizes[1] / 2;

    __half* d_h;   cudaGetSymbolAddress((void**)&d_h,   g_h);
    __half* d_agg; cudaGetSymbolAddress((void**)&d_agg, g_agg);
    __half* d_t;   cudaGetSymbolAddress((void**)&d_t,   g_t);

    const int T = 256;
    const int halfE = (E + 1) / 2;

    // Side stream for GEMM1 (independent of CSR build) — fork/join via events.
    cudaStream_t s1;
    cudaStreamCreateWithFlags(&s1, cudaStreamNonBlocking);
    cudaEvent_t e_fork, e_join;
    cudaEventCreateWithFlags(&e_fork, cudaEventDisableTiming);
    cudaEventCreateWithFlags(&e_join, cudaEventDisableTiming);

    cudaEventRecord(e_fork, 0);
    cudaStreamWaitEvent(s1, e_fork, 0);
    {
        dim3 grid((n + 255) / 256, 2);
        k_gemm_mma<128, float, __half><<<grid, 256, 0, s1>>>(x, W1, d_h, n);
    }
    cudaEventRecord(e_join, s1);

    // CSR build + dinv on the main stream, concurrent with GEMM1 (3 kernels)
    k_count_f<<<(halfE + T - 1) / T, T>>>(ei, E, n);
    k_scan<<<NBLK_SCAN, SCAN_BLK>>>(n, E);
    k_fill_f<<<(halfE + T - 1) / T, T>>>(ei, E, n);

    cudaStreamWaitEvent(0, e_join, 0);

    // aggregate layer 1 (fused self-loop + bias + relu), fp16 -> fp16
    k_agg_h<128, true, __half><<<(n + 7) / 8, 256>>>(d_h, d_agg, b1, n);

    // layer 2: t = relu_h @ W2 (fp16 in, fp16 out)
    {
        dim3 grid((n + 255) / 256, 1);
        k_gemm_mma<64, __half, __half><<<grid, 256>>>(d_agg, W2, d_t, n);
    }

    // aggregate layer 2 directly into d_out (fused bias), fp16 -> fp32
    k_agg_h<64, false, float><<<(n + 7) / 8, 256>>>(d_t, out, b2, n);

    cudaEventDestroy(e_fork);
    cudaEventDestroy(e_join);
    cudaStreamDestroy(s1);
}